// round 8
// baseline (speedup 1.0000x reference)
#include <cuda_runtime.h>
#include <cstdint>
#include <cstddef>

#define B_      4
#define TCMP    2048
#define C_      2048
#define H_      16
#define KV_     8
#define TW      1024
#define D_      128
#define NSEL    512
#define OUTLEN  2560
#define M_      (B_*TCMP)
#define K1      (2*C_)
#define SCALE_F 0.08838834764831845f

__device__ float  g_h[(size_t)M_ * C_];
__device__ float  g_xmcmp[(size_t)M_ * C_];
__device__ float  g_w[(size_t)B_ * H_ * TW * TCMP];   // 512 MB: full softmax weights
__device__ float  g_imp[B_ * TCMP];
__device__ int    g_seldesc[B_ * NSEL];
__device__ int    g_seqsel[B_ * NSEL];
__device__ int    g_keepdst[B_ * TCMP];

__device__ __forceinline__ float siluf(float x) { return x / (1.f + expf(-x)); }
__device__ __forceinline__ uint32_t f2tf(float x) {
    uint32_t u; asm("cvt.rna.tf32.f32 %0, %1;" : "=r"(u) : "f"(x)); return u;
}
__device__ __forceinline__ void split3(float x, uint32_t& hi, uint32_t& lo) {
    hi = f2tf(x);
    lo = f2tf(x - __uint_as_float(hi));
}
__device__ __forceinline__ void mma8(float* c, const uint32_t* a, const uint32_t* b) {
    asm volatile("mma.sync.aligned.m16n8k8.row.col.f32.tf32.tf32.f32 "
                 "{%0,%1,%2,%3}, {%4,%5,%6,%7}, {%8,%9}, {%0,%1,%2,%3};"
                 : "+f"(c[0]), "+f"(c[1]), "+f"(c[2]), "+f"(c[3])
                 : "r"(a[0]), "r"(a[1]), "r"(a[2]), "r"(a[3]), "r"(b[0]), "r"(b[1]));
}

// ---------------- importance pass 1: fp32 scores + softmax (w = e / Z) ----------------
#define IQ   16
#define KT   512
#define DC   32
#define QS_OFF   (IQ*TCMP)
#define KMS_OFF  (QS_OFF + IQ*D_)
#define IVZ_OFF  (KMS_OFF + KT*33)
#define IMP_SMEM ((IVZ_OFF + IQ) * 4)

__global__ __launch_bounds__(256, 1)
void importance_kernel(const float* __restrict__ q_w, const float* __restrict__ km) {
    extern __shared__ float sm[];
    const int tid = threadIdx.x;
    const int bh = blockIdx.y;
    const int b = bh >> 4, h = bh & 15;
    const int qbase = blockIdx.x * IQ;
    const float* qp = q_w + (((size_t)(b * H_ + h)) * TW + qbase) * D_;
    const float* kp = km + ((size_t)(b * KV_ + (h >> 1))) * TCMP * D_;

    for (int i = tid; i < IQ * D_ / 4; i += 256)
        ((float4*)(sm + QS_OFF))[i] = ((const float4*)qp)[i];

    const int qg = tid >> 6, kg = tid & 63;
    float* sc  = sm;
    float* kms = sm + KMS_OFF;

    for (int kt = 0; kt < TCMP / KT; kt++) {
        float acc[4][8];
        #pragma unroll
        for (int qi = 0; qi < 4; qi++)
            #pragma unroll
            for (int j = 0; j < 8; j++) acc[qi][j] = 0.f;

        for (int dc = 0; dc < D_ / DC; dc++) {
            __syncthreads();
            for (int r = tid; r < KT; r += 256) {
                const float* src = kp + (size_t)(kt * KT + r) * D_ + dc * DC;
                #pragma unroll
                for (int f = 0; f < DC / 4; f++) {
                    float4 v = ((const float4*)src)[f];
                    float* d = kms + r * 33 + f * 4;
                    d[0] = v.x; d[1] = v.y; d[2] = v.z; d[3] = v.w;
                }
            }
            __syncthreads();
            // strictly ascending d accumulation (single FFMA chain, matches SGEMM)
            #pragma unroll
            for (int d = 0; d < DC; d++) {
                float qv[4];
                #pragma unroll
                for (int qi = 0; qi < 4; qi++)
                    qv[qi] = sm[QS_OFF + (qg * 4 + qi) * D_ + dc * DC + d];
                #pragma unroll
                for (int j = 0; j < 8; j++) {
                    float kv = kms[(j * 64 + kg) * 33 + d];
                    #pragma unroll
                    for (int qi = 0; qi < 4; qi++) acc[qi][j] += qv[qi] * kv;
                }
            }
        }
        #pragma unroll
        for (int qi = 0; qi < 4; qi++)
            #pragma unroll
            for (int j = 0; j < 8; j++)
                sc[(qg * 4 + qi) * TCMP + kt * KT + j * 64 + kg] = acc[qi][j];
    }
    __syncthreads();

    // softmax: scale, exact max, expf (libdevice = XLA), Z (order rank-neutral)
    const int warp = tid >> 5, lane = tid & 31;
    for (int r = warp; r < IQ; r += 8) {
        float m = -1e30f;
        for (int i = lane; i < TCMP; i += 32) {
            float t = sc[r * TCMP + i] * SCALE_F;
            sc[r * TCMP + i] = t;
            m = fmaxf(m, t);
        }
        #pragma unroll
        for (int o = 16; o; o >>= 1) m = fmaxf(m, __shfl_xor_sync(~0u, m, o));
        float z = 0.f;
        for (int i = lane; i < TCMP; i += 32) {
            float e = expf(sc[r * TCMP + i] - m);
            sc[r * TCMP + i] = e;
            z += e;
        }
        #pragma unroll
        for (int o = 16; o; o >>= 1) z += __shfl_xor_sync(~0u, z, o);
        if (lane == 0) sm[IVZ_OFF + r] = z;   // store Z itself
    }
    __syncthreads();

    // w = e / Z  (true fp32 division, as jax.nn.softmax emits)
    float* wp = g_w + ((size_t)bh * TW + qbase) * TCMP;
    for (int idx = tid; idx < IQ * TCMP; idx += 256) {
        const int r = idx >> 11, k = idx & (TCMP - 1);
        wp[(size_t)r * TCMP + k] = sc[r * TCMP + k] / sm[IVZ_OFF + r];
    }
}

// ------- pass 2: XLA column-reduction emulation -------------------------------------
// q-sum: lane partials over rows j+32*i (i ascending), then shfl-down tree 16,8,4,2,1.
// h-mean: 16 partials (+16 zeros), same tree (effective 8,4,2,1), then * 1/16.
__global__ __launch_bounds__(256)
void reduce_imp_kernel() {
    const int i = blockIdx.x * blockDim.x + threadIdx.x;
    if (i >= B_ * TCMP) return;
    const int b = i >> 11, k = i & (TCMP - 1);
    float S[16];
    for (int h = 0; h < H_; h++) {
        const float* p = g_w + ((size_t)(b * H_ + h) * TW) * TCMP + k;
        float part[32];
        #pragma unroll
        for (int j = 0; j < 32; j++) part[j] = 0.f;
        for (int ii = 0; ii < 32; ii++) {
            #pragma unroll
            for (int j = 0; j < 32; j++)
                part[j] += p[(size_t)(j + 32 * ii) * TCMP];
        }
        #pragma unroll
        for (int off = 16; off >= 1; off >>= 1)
            #pragma unroll
            for (int j = 0; j < 16; j++)
                if (j < off) part[j] = part[j] + part[j + off];
        S[h] = part[0];
    }
    #pragma unroll
    for (int off = 8; off >= 1; off >>= 1)
        #pragma unroll
        for (int j = 0; j < 8; j++)
            if (j < off) S[j] = S[j] + S[j + off];
    g_imp[i] = S[0] / 16.f;
}

// ---------------- top-k (jax order: value desc, index tiebreak, f32 compare) ----------
__global__ __launch_bounds__(1024)
void topk_kernel() {
    __shared__ float v[TCMP];
    __shared__ int rnk[TCMP];
    __shared__ int selm[TCMP];
    const int b = blockIdx.x, tid = threadIdx.x;
    for (int i = tid; i < TCMP; i += 1024) v[i] = g_imp[b * TCMP + i];
    __syncthreads();
    for (int t = tid; t < TCMP; t += 1024) {
        float x = v[t];
        int r = 0;
        for (int j = 0; j < TCMP; j++) {
            float y = v[j];
            r += (y > x) || (y == x && j < t);
        }
        rnk[t] = r;
    }
    __syncthreads();
    for (int t = tid; t < TCMP; t += 1024) selm[t] = rnk[t] < NSEL;
    __syncthreads();
    for (int t = tid; t < TCMP; t += 1024) {
        int cb = 0;
        for (int j = 0; j < t; j++) cb += selm[j];
        if (selm[t]) {
            g_seldesc[b * NSEL + rnk[t]] = t;
            g_seqsel[b * NSEL + cb] = t;
            g_keepdst[b * TCMP + t] = -1;
        } else {
            g_keepdst[b * TCMP + t] = t + cb;
        }
    }
}

// ---------------- GEMM 1: fused gate/up, 3xTF32 (near-exact f32) ----------------
#define BM 128
#define BN 64
#define BK 16

__global__ __launch_bounds__(256, 1)
void gemm1_kernel(const float* __restrict__ X,
                  const float* __restrict__ Wg, const float* __restrict__ Wu) {
    __shared__ float As[2][BK][BM + 4];
    __shared__ float Bs[2][2][BK][BN + 4];
    const int tid = threadIdx.x, bid = blockIdx.x;
    const int mt = (bid >> 9) * 16 + (bid & 15);
    const int nt = (bid >> 4) & 31;
    const float* Ap  = X  + (size_t)mt * BM * K1;
    const float* Bgp = Wg + (size_t)nt * BN * K1;
    const float* Bup = Wu + (size_t)nt * BN * K1;
    const int warp = tid >> 5, lane = tid & 31;
    const int wm = warp & 3, wn = warp >> 2;
    const int lt = lane & 3, lg = lane >> 2;

    float accG[2][4][4], accU[2][4][4];
    #pragma unroll
    for (int a = 0; a < 2; a++)
        #pragma unroll
        for (int b2 = 0; b2 < 4; b2++)
            #pragma unroll
            for (int c = 0; c < 4; c++) { accG[a][b2][c] = 0.f; accU[a][b2][c] = 0.f; }

    float4 ra0, ra1, rg, ru;
    const int lrow = tid >> 2, lc0 = (tid & 3) * 4;

    auto ldg_tile = [&](int kb) {
        const float* a = Ap + kb * BK;
        ra0 = *(const float4*)(a + (size_t)lrow * K1 + lc0);
        ra1 = *(const float4*)(a + (size_t)(lrow + 64) * K1 + lc0);
        rg  = *(const float4*)(Bgp + kb * BK + (size_t)lrow * K1 + lc0);
        ru  = *(const float4*)(Bup + kb * BK + (size_t)lrow * K1 + lc0);
    };
    auto sts_tile = [&](int s) {
        const float *p0 = (const float*)&ra0, *p1 = (const float*)&ra1;
        const float *pg = (const float*)&rg,  *pu = (const float*)&ru;
        #pragma unroll
        for (int j = 0; j < 4; j++) {
            As[s][lc0 + j][lrow]      = p0[j];
            As[s][lc0 + j][lrow + 64] = p1[j];
            Bs[s][0][lc0 + j][lrow]   = pg[j];
            Bs[s][1][lc0 + j][lrow]   = pu[j];
        }
    };
    auto compute = [&](int s) {
        #pragma unroll
        for (int ks = 0; ks < 2; ks++) {
            const int k0 = ks * 8;
            uint32_t ah[2][4], al[2][4];
            #pragma unroll
            for (int mi = 0; mi < 2; mi++) {
                const int mb = wm * 32 + mi * 16;
                split3(As[s][k0 + lt][mb + lg],         ah[mi][0], al[mi][0]);
                split3(As[s][k0 + lt][mb + lg + 8],     ah[mi][1], al[mi][1]);
                split3(As[s][k0 + 4 + lt][mb + lg],     ah[mi][2], al[mi][2]);
                split3(As[s][k0 + 4 + lt][mb + lg + 8], ah[mi][3], al[mi][3]);
            }
            #pragma unroll
            for (int ni = 0; ni < 4; ni++) {
                const int nb = wn * 32 + ni * 8;
                uint32_t bh2[2][2], bl2[2][2];
                split3(Bs[s][0][k0 + lt][nb + lg],     bh2[0][0], bl2[0][0]);
                split3(Bs[s][0][k0 + 4 + lt][nb + lg], bh2[0][1], bl2[0][1]);
                split3(Bs[s][1][k0 + lt][nb + lg],     bh2[1][0], bl2[1][0]);
                split3(Bs[s][1][k0 + 4 + lt][nb + lg], bh2[1][1], bl2[1][1]);
                #pragma unroll
                for (int mi = 0; mi < 2; mi++) {
                    mma8(accG[mi][ni], ah[mi], bh2[0]);
                    mma8(accG[mi][ni], ah[mi], bl2[0]);
                    mma8(accG[mi][ni], al[mi], bh2[0]);
                    mma8(accU[mi][ni], ah[mi], bh2[1]);
                    mma8(accU[mi][ni], ah[mi], bl2[1]);
                    mma8(accU[mi][ni], al[mi], bh2[1]);
                }
            }
        }
    };

    ldg_tile(0); sts_tile(0); __syncthreads();
    const int KIT = K1 / BK;
    for (int kb = 0; kb < KIT; kb++) {
        const int s = kb & 1;
        if (kb + 1 < KIT) ldg_tile(kb + 1);
        compute(s);
        if (kb + 1 < KIT) { __syncthreads(); sts_tile(s ^ 1); __syncthreads(); }
    }

    #pragma unroll
    for (int mi = 0; mi < 2; mi++)
        #pragma unroll
        for (int ni = 0; ni < 4; ni++) {
            const int r = mt * BM + wm * 32 + mi * 16 + lg;
            const int c = nt * BN + wn * 32 + ni * 8 + lt * 2;
            #pragma unroll
            for (int half = 0; half < 2; half++) {
                const int rr = r + half * 8;
                float g0 = accG[mi][ni][half * 2], g1 = accG[mi][ni][half * 2 + 1];
                float u0 = accU[mi][ni][half * 2], u1 = accU[mi][ni][half * 2 + 1];
                *(float2*)(g_h + (size_t)rr * C_ + c) =
                    make_float2(siluf(g0) * u0, siluf(g1) * u1);
            }
        }
}

// ---------------- GEMM 2: down-proj, 3xTF32 ----------------
#define K2 2048
__global__ __launch_bounds__(256, 1)
void gemm2_kernel(const float* __restrict__ Wd) {
    __shared__ float As[2][BK][BM + 4];
    __shared__ float Bs[2][BK][BN + 4];
    const int tid = threadIdx.x, bid = blockIdx.x;
    const int nt = bid & 31, mt = bid >> 5;
    const float* Ap = g_h + (size_t)mt * BM * K2;
    const float* Bp = Wd  + (size_t)nt * BN * K2;
    const int warp = tid >> 5, lane = tid & 31;
    const int wm = warp & 3, wn = warp >> 2;
    const int lt = lane & 3, lg = lane >> 2;

    float acc[2][4][4];
    #pragma unroll
    for (int a = 0; a < 2; a++)
        #pragma unroll
        for (int b2 = 0; b2 < 4; b2++)
            #pragma unroll
            for (int c = 0; c < 4; c++) acc[a][b2][c] = 0.f;

    float4 ra0, ra1, rb;
    const int lrow = tid >> 2, lc0 = (tid & 3) * 4;

    auto ldg_tile = [&](int kb) {
        const float* a = Ap + kb * BK;
        ra0 = *(const float4*)(a + (size_t)lrow * K2 + lc0);
        ra1 = *(const float4*)(a + (size_t)(lrow + 64) * K2 + lc0);
        rb  = *(const float4*)(Bp + kb * BK + (size_t)lrow * K2 + lc0);
    };
    auto sts_tile = [&](int s) {
        const float *p0 = (const float*)&ra0, *p1 = (const float*)&ra1;
        const float *pb = (const float*)&rb;
        #pragma unroll
        for (int j = 0; j < 4; j++) {
            As[s][lc0 + j][lrow]      = p0[j];
            As[s][lc0 + j][lrow + 64] = p1[j];
            Bs[s][lc0 + j][lrow]      = pb[j];
        }
    };
    auto compute = [&](int s) {
        #pragma unroll
        for (int ks = 0; ks < 2; ks++) {
            const int k0 = ks * 8;
            uint32_t ah[2][4], al[2][4];
            #pragma unroll
            for (int mi = 0; mi < 2; mi++) {
                const int mb = wm * 32 + mi * 16;
                split3(As[s][k0 + lt][mb + lg],         ah[mi][0], al[mi][0]);
                split3(As[s][k0 + lt][mb + lg + 8],     ah[mi][1], al[mi][1]);
                split3(As[s][k0 + 4 + lt][mb + lg],     ah[mi][2], al[mi][2]);
                split3(As[s][k0 + 4 + lt][mb + lg + 8], ah[mi][3], al[mi][3]);
            }
            #pragma unroll
            for (int ni = 0; ni < 4; ni++) {
                const int nb = wn * 32 + ni * 8;
                uint32_t bh2[2], bl2[2];
                split3(Bs[s][k0 + lt][nb + lg],     bh2[0], bl2[0]);
                split3(Bs[s][k0 + 4 + lt][nb + lg], bh2[1], bl2[1]);
                #pragma unroll
                for (int mi = 0; mi < 2; mi++) {
                    mma8(acc[mi][ni], ah[mi], bh2);
                    mma8(acc[mi][ni], ah[mi], bl2);
                    mma8(acc[mi][ni], al[mi], bh2);
                }
            }
        }
    };

    ldg_tile(0); sts_tile(0); __syncthreads();
    const int KIT = K2 / BK;
    for (int kb = 0; kb < KIT; kb++) {
        const int s = kb & 1;
        if (kb + 1 < KIT) ldg_tile(kb + 1);
        compute(s);
        if (kb + 1 < KIT) { __syncthreads(); sts_tile(s ^ 1); __syncthreads(); }
    }

    #pragma unroll
    for (int mi = 0; mi < 2; mi++)
        #pragma unroll
        for (int ni = 0; ni < 4; ni++) {
            const int r = mt * BM + wm * 32 + mi * 16 + lg;
            const int c = nt * BN + wn * 32 + ni * 8 + lt * 2;
            #pragma unroll
            for (int half = 0; half < 2; half++) {
                const int rr = r + half * 8;
                *(float2*)(g_xmcmp + (size_t)rr * C_ + c) =
                    make_float2(siluf(acc[mi][ni][half * 2]),
                                siluf(acc[mi][ni][half * 2 + 1]));
            }
        }
}

// ---------------- interleave ----------------
__global__ __launch_bounds__(256)
void interleave_kernel(const float* __restrict__ x_m, float* __restrict__ out) {
    const int b = blockIdx.y, i = blockIdx.x, tid = threadIdx.x;
    if (i < TCMP) {
        const int dst = g_keepdst[b * TCMP + i];
        if (dst < 0) return;
        const float4* s = (const float4*)(g_xmcmp + ((size_t)(b * TCMP + i)) * C_);
        float4* d = (float4*)(out + ((size_t)(b * OUTLEN + dst)) * C_);
        for (int j = tid; j < C_ / 4; j += 256) d[j] = s[j];
    } else {
        const int k = i - TCMP;
        const int sk  = g_seqsel[b * NSEL + k];
        const int pos = sk + k;
        const int src = g_seldesc[b * NSEL + k];
        const float4* s = (const float4*)(x_m + ((size_t)(b * 2 * TCMP) + 2 * src) * C_);
        float4* d = (float4*)(out + ((size_t)(b * OUTLEN + pos)) * C_);
        for (int j = tid; j < 2 * C_ / 4; j += 256) d[j] = s[j];
    }
}

// ---------------- launch ----------------
extern "C" void kernel_launch(void* const* d_in, const int* in_sizes, int n_in,
                              void* d_out, int out_size) {
    const float* x_m = (const float*)d_in[0];
    const float* q_w = (const float*)d_in[1];
    const float* km  = (const float*)d_in[2];
    const float* Wg  = (const float*)d_in[3];
    const float* Wu  = (const float*)d_in[4];
    const float* Wd  = (const float*)d_in[5];
    float* out = (float*)d_out;

    cudaFuncSetAttribute(importance_kernel,
                         cudaFuncAttributeMaxDynamicSharedMemorySize, IMP_SMEM);

    importance_kernel<<<dim3(TW / IQ, B_ * H_), 256, IMP_SMEM>>>(q_w, km);
    reduce_imp_kernel<<<(B_ * TCMP + 255) / 256, 256>>>();
    topk_kernel<<<B_, 1024>>>();
    gemm1_kernel<<<2048, 256>>>(x_m, Wg, Wu);
    gemm2_kernel<<<2048, 256>>>(Wd);
    interleave_kernel<<<dim3(TCMP + NSEL, B_), 256>>>(x_m, out);
}

// round 9
// speedup vs baseline: 1.3470x; 1.3470x over previous
#include <cuda_runtime.h>
#include <cstdint>
#include <cstddef>

#define B_      4
#define TCMP    2048
#define C_      2048
#define H_      16
#define KV_     8
#define TW      1024
#define D_      128
#define NSEL    512
#define OUTLEN  2560
#define M_      (B_*TCMP)
#define K1      (2*C_)
#define SCALE_F 0.08838834764831845f

__device__ float  g_h[(size_t)M_ * C_];
__device__ float  g_xmcmp[(size_t)M_ * C_];
__device__ float  g_w[(size_t)B_ * H_ * TW * TCMP];   // 512 MB: full softmax weights
__device__ float  g_imp[B_ * TCMP];
__device__ int    g_seldesc[B_ * NSEL];
__device__ int    g_seqsel[B_ * NSEL];
__device__ int    g_keepdst[B_ * TCMP];

__device__ __forceinline__ float siluf(float x) { return x / (1.f + expf(-x)); }
__device__ __forceinline__ uint32_t f2tf(float x) {
    uint32_t u; asm("cvt.rna.tf32.f32 %0, %1;" : "=r"(u) : "f"(x)); return u;
}
__device__ __forceinline__ void mma8(float* c, const uint32_t* a, const uint32_t* b) {
    asm volatile("mma.sync.aligned.m16n8k8.row.col.f32.tf32.tf32.f32 "
                 "{%0,%1,%2,%3}, {%4,%5,%6,%7}, {%8,%9}, {%0,%1,%2,%3};"
                 : "+f"(c[0]), "+f"(c[1]), "+f"(c[2]), "+f"(c[3])
                 : "r"(a[0]), "r"(a[1]), "r"(a[2]), "r"(a[3]), "r"(b[0]), "r"(b[1]));
}

// ---------------- importance pass 1: fp32 scores + softmax (w = e / Z) ----------------
// FROZEN: this path bit-matches the reference; do not alter numerics.
#define IQ   16
#define KT   512
#define DC   32
#define QS_OFF   (IQ*TCMP)
#define KMS_OFF  (QS_OFF + IQ*D_)
#define IVZ_OFF  (KMS_OFF + KT*33)
#define IMP_SMEM ((IVZ_OFF + IQ) * 4)

__global__ __launch_bounds__(256, 1)
void importance_kernel(const float* __restrict__ q_w, const float* __restrict__ km) {
    extern __shared__ float sm[];
    const int tid = threadIdx.x;
    const int bh = blockIdx.y;
    const int b = bh >> 4, h = bh & 15;
    const int qbase = blockIdx.x * IQ;
    const float* qp = q_w + (((size_t)(b * H_ + h)) * TW + qbase) * D_;
    const float* kp = km + ((size_t)(b * KV_ + (h >> 1))) * TCMP * D_;

    for (int i = tid; i < IQ * D_ / 4; i += 256)
        ((float4*)(sm + QS_OFF))[i] = ((const float4*)qp)[i];

    const int qg = tid >> 6, kg = tid & 63;
    float* sc  = sm;
    float* kms = sm + KMS_OFF;

    for (int kt = 0; kt < TCMP / KT; kt++) {
        float acc[4][8];
        #pragma unroll
        for (int qi = 0; qi < 4; qi++)
            #pragma unroll
            for (int j = 0; j < 8; j++) acc[qi][j] = 0.f;

        for (int dc = 0; dc < D_ / DC; dc++) {
            __syncthreads();
            for (int r = tid; r < KT; r += 256) {
                const float* src = kp + (size_t)(kt * KT + r) * D_ + dc * DC;
                #pragma unroll
                for (int f = 0; f < DC / 4; f++) {
                    float4 v = ((const float4*)src)[f];
                    float* d = kms + r * 33 + f * 4;
                    d[0] = v.x; d[1] = v.y; d[2] = v.z; d[3] = v.w;
                }
            }
            __syncthreads();
            #pragma unroll
            for (int d = 0; d < DC; d++) {
                float qv[4];
                #pragma unroll
                for (int qi = 0; qi < 4; qi++)
                    qv[qi] = sm[QS_OFF + (qg * 4 + qi) * D_ + dc * DC + d];
                #pragma unroll
                for (int j = 0; j < 8; j++) {
                    float kv = kms[(j * 64 + kg) * 33 + d];
                    #pragma unroll
                    for (int qi = 0; qi < 4; qi++) acc[qi][j] += qv[qi] * kv;
                }
            }
        }
        #pragma unroll
        for (int qi = 0; qi < 4; qi++)
            #pragma unroll
            for (int j = 0; j < 8; j++)
                sc[(qg * 4 + qi) * TCMP + kt * KT + j * 64 + kg] = acc[qi][j];
    }
    __syncthreads();

    const int warp = tid >> 5, lane = tid & 31;
    for (int r = warp; r < IQ; r += 8) {
        float m = -1e30f;
        for (int i = lane; i < TCMP; i += 32) {
            float t = sc[r * TCMP + i] * SCALE_F;
            sc[r * TCMP + i] = t;
            m = fmaxf(m, t);
        }
        #pragma unroll
        for (int o = 16; o; o >>= 1) m = fmaxf(m, __shfl_xor_sync(~0u, m, o));
        float z = 0.f;
        for (int i = lane; i < TCMP; i += 32) {
            float e = expf(sc[r * TCMP + i] - m);
            sc[r * TCMP + i] = e;
            z += e;
        }
        #pragma unroll
        for (int o = 16; o; o >>= 1) z += __shfl_xor_sync(~0u, z, o);
        if (lane == 0) sm[IVZ_OFF + r] = z;
    }
    __syncthreads();

    float* wp = g_w + ((size_t)bh * TW + qbase) * TCMP;
    for (int idx = tid; idx < IQ * TCMP; idx += 256) {
        const int r = idx >> 11, k = idx & (TCMP - 1);
        wp[(size_t)r * TCMP + k] = sc[r * TCMP + k] / sm[IVZ_OFF + r];
    }
}

// ------- pass 2: XLA column-reduction emulation (FROZEN) -------------------------------
__global__ __launch_bounds__(256)
void reduce_imp_kernel() {
    const int i = blockIdx.x * blockDim.x + threadIdx.x;
    if (i >= B_ * TCMP) return;
    const int b = i >> 11, k = i & (TCMP - 1);
    float S[16];
    for (int h = 0; h < H_; h++) {
        const float* p = g_w + ((size_t)(b * H_ + h) * TW) * TCMP + k;
        float part[32];
        #pragma unroll
        for (int j = 0; j < 32; j++) part[j] = 0.f;
        for (int ii = 0; ii < 32; ii++) {
            #pragma unroll
            for (int j = 0; j < 32; j++)
                part[j] += p[(size_t)(j + 32 * ii) * TCMP];
        }
        #pragma unroll
        for (int off = 16; off >= 1; off >>= 1)
            #pragma unroll
            for (int j = 0; j < 16; j++)
                if (j < off) part[j] = part[j] + part[j + off];
        S[h] = part[0];
    }
    #pragma unroll
    for (int off = 8; off >= 1; off >>= 1)
        #pragma unroll
        for (int j = 0; j < 8; j++)
            if (j < off) S[j] = S[j] + S[j + off];
    g_imp[i] = S[0] / 16.f;
}

// ---------------- top-k (jax order: value desc, index tiebreak, f32 compare) ----------
__global__ __launch_bounds__(1024)
void topk_kernel() {
    __shared__ float v[TCMP];
    __shared__ int rnk[TCMP];
    __shared__ int selm[TCMP];
    const int b = blockIdx.x, tid = threadIdx.x;
    for (int i = tid; i < TCMP; i += 1024) v[i] = g_imp[b * TCMP + i];
    __syncthreads();
    for (int t = tid; t < TCMP; t += 1024) {
        float x = v[t];
        int r = 0;
        for (int j = 0; j < TCMP; j++) {
            float y = v[j];
            r += (y > x) || (y == x && j < t);
        }
        rnk[t] = r;
    }
    __syncthreads();
    for (int t = tid; t < TCMP; t += 1024) selm[t] = rnk[t] < NSEL;
    __syncthreads();
    for (int t = tid; t < TCMP; t += 1024) {
        int cb = 0;
        for (int j = 0; j < t; j++) cb += selm[j];
        if (selm[t]) {
            g_seldesc[b * NSEL + rnk[t]] = t;
            g_seqsel[b * NSEL + cb] = t;
            g_keepdst[b * TCMP + t] = -1;
        } else {
            g_keepdst[b * TCMP + t] = t + cb;
        }
    }
}

// ---------------- GEMM 1: fused gate/up, 1xTF32 ----------------
#define BM 128
#define BN 64
#define BK 16

__global__ __launch_bounds__(256, 2)
void gemm1_kernel(const float* __restrict__ X,
                  const float* __restrict__ Wg, const float* __restrict__ Wu) {
    __shared__ float As[2][BK][BM + 4];
    __shared__ float Bs[2][2][BK][BN + 4];
    const int tid = threadIdx.x, bid = blockIdx.x;
    const int mt = (bid >> 9) * 16 + (bid & 15);
    const int nt = (bid >> 4) & 31;
    const float* Ap  = X  + (size_t)mt * BM * K1;
    const float* Bgp = Wg + (size_t)nt * BN * K1;
    const float* Bup = Wu + (size_t)nt * BN * K1;
    const int warp = tid >> 5, lane = tid & 31;
    const int wm = warp & 3, wn = warp >> 2;
    const int lt = lane & 3, lg = lane >> 2;

    float accG[2][4][4], accU[2][4][4];
    #pragma unroll
    for (int a = 0; a < 2; a++)
        #pragma unroll
        for (int b2 = 0; b2 < 4; b2++)
            #pragma unroll
            for (int c = 0; c < 4; c++) { accG[a][b2][c] = 0.f; accU[a][b2][c] = 0.f; }

    float4 ra0, ra1, rg, ru;
    const int lrow = tid >> 2, lc0 = (tid & 3) * 4;

    auto ldg_tile = [&](int kb) {
        const float* a = Ap + kb * BK;
        ra0 = *(const float4*)(a + (size_t)lrow * K1 + lc0);
        ra1 = *(const float4*)(a + (size_t)(lrow + 64) * K1 + lc0);
        rg  = *(const float4*)(Bgp + kb * BK + (size_t)lrow * K1 + lc0);
        ru  = *(const float4*)(Bup + kb * BK + (size_t)lrow * K1 + lc0);
    };
    auto sts_tile = [&](int s) {
        const float *p0 = (const float*)&ra0, *p1 = (const float*)&ra1;
        const float *pg = (const float*)&rg,  *pu = (const float*)&ru;
        #pragma unroll
        for (int j = 0; j < 4; j++) {
            As[s][lc0 + j][lrow]      = p0[j];
            As[s][lc0 + j][lrow + 64] = p1[j];
            Bs[s][0][lc0 + j][lrow]   = pg[j];
            Bs[s][1][lc0 + j][lrow]   = pu[j];
        }
    };
    auto compute = [&](int s) {
        #pragma unroll
        for (int ks = 0; ks < 2; ks++) {
            const int k0 = ks * 8;
            uint32_t a[2][4];
            #pragma unroll
            for (int mi = 0; mi < 2; mi++) {
                const int mb = wm * 32 + mi * 16;
                a[mi][0] = f2tf(As[s][k0 + lt][mb + lg]);
                a[mi][1] = f2tf(As[s][k0 + lt][mb + lg + 8]);
                a[mi][2] = f2tf(As[s][k0 + 4 + lt][mb + lg]);
                a[mi][3] = f2tf(As[s][k0 + 4 + lt][mb + lg + 8]);
            }
            #pragma unroll
            for (int ni = 0; ni < 4; ni++) {
                const int nb = wn * 32 + ni * 8;
                uint32_t bg[2], bu[2];
                bg[0] = f2tf(Bs[s][0][k0 + lt][nb + lg]);
                bg[1] = f2tf(Bs[s][0][k0 + 4 + lt][nb + lg]);
                bu[0] = f2tf(Bs[s][1][k0 + lt][nb + lg]);
                bu[1] = f2tf(Bs[s][1][k0 + 4 + lt][nb + lg]);
                #pragma unroll
                for (int mi = 0; mi < 2; mi++) {
                    mma8(accG[mi][ni], a[mi], bg);
                    mma8(accU[mi][ni], a[mi], bu);
                }
            }
        }
    };

    ldg_tile(0); sts_tile(0); __syncthreads();
    const int KIT = K1 / BK;
    for (int kb = 0; kb < KIT; kb++) {
        const int s = kb & 1;
        if (kb + 1 < KIT) ldg_tile(kb + 1);
        compute(s);
        if (kb + 1 < KIT) { __syncthreads(); sts_tile(s ^ 1); __syncthreads(); }
    }

    #pragma unroll
    for (int mi = 0; mi < 2; mi++)
        #pragma unroll
        for (int ni = 0; ni < 4; ni++) {
            const int r = mt * BM + wm * 32 + mi * 16 + lg;
            const int c = nt * BN + wn * 32 + ni * 8 + lt * 2;
            #pragma unroll
            for (int half = 0; half < 2; half++) {
                const int rr = r + half * 8;
                float g0 = accG[mi][ni][half * 2], g1 = accG[mi][ni][half * 2 + 1];
                float u0 = accU[mi][ni][half * 2], u1 = accU[mi][ni][half * 2 + 1];
                *(float2*)(g_h + (size_t)rr * C_ + c) =
                    make_float2(siluf(g0) * u0, siluf(g1) * u1);
            }
        }
}

// ---------------- GEMM 2: down-proj, 1xTF32 ----------------
#define K2 2048
__global__ __launch_bounds__(256, 2)
void gemm2_kernel(const float* __restrict__ Wd) {
    __shared__ float As[2][BK][BM + 4];
    __shared__ float Bs[2][BK][BN + 4];
    const int tid = threadIdx.x, bid = blockIdx.x;
    const int nt = bid & 31, mt = bid >> 5;
    const float* Ap = g_h + (size_t)mt * BM * K2;
    const float* Bp = Wd  + (size_t)nt * BN * K2;
    const int warp = tid >> 5, lane = tid & 31;
    const int wm = warp & 3, wn = warp >> 2;
    const int lt = lane & 3, lg = lane >> 2;

    float acc[2][4][4];
    #pragma unroll
    for (int a = 0; a < 2; a++)
        #pragma unroll
        for (int b2 = 0; b2 < 4; b2++)
            #pragma unroll
            for (int c = 0; c < 4; c++) acc[a][b2][c] = 0.f;

    float4 ra0, ra1, rb;
    const int lrow = tid >> 2, lc0 = (tid & 3) * 4;

    auto ldg_tile = [&](int kb) {
        const float* a = Ap + kb * BK;
        ra0 = *(const float4*)(a + (size_t)lrow * K2 + lc0);
        ra1 = *(const float4*)(a + (size_t)(lrow + 64) * K2 + lc0);
        rb  = *(const float4*)(Bp + kb * BK + (size_t)lrow * K2 + lc0);
    };
    auto sts_tile = [&](int s) {
        const float *p0 = (const float*)&ra0, *p1 = (const float*)&ra1;
        const float *pb = (const float*)&rb;
        #pragma unroll
        for (int j = 0; j < 4; j++) {
            As[s][lc0 + j][lrow]      = p0[j];
            As[s][lc0 + j][lrow + 64] = p1[j];
            Bs[s][lc0 + j][lrow]      = pb[j];
        }
    };
    auto compute = [&](int s) {
        #pragma unroll
        for (int ks = 0; ks < 2; ks++) {
            const int k0 = ks * 8;
            uint32_t a[2][4];
            #pragma unroll
            for (int mi = 0; mi < 2; mi++) {
                const int mb = wm * 32 + mi * 16;
                a[mi][0] = f2tf(As[s][k0 + lt][mb + lg]);
                a[mi][1] = f2tf(As[s][k0 + lt][mb + lg + 8]);
                a[mi][2] = f2tf(As[s][k0 + 4 + lt][mb + lg]);
                a[mi][3] = f2tf(As[s][k0 + 4 + lt][mb + lg + 8]);
            }
            #pragma unroll
            for (int ni = 0; ni < 4; ni++) {
                const int nb = wn * 32 + ni * 8;
                uint32_t bb[2];
                bb[0] = f2tf(Bs[s][k0 + lt][nb + lg]);
                bb[1] = f2tf(Bs[s][k0 + 4 + lt][nb + lg]);
                #pragma unroll
                for (int mi = 0; mi < 2; mi++) mma8(acc[mi][ni], a[mi], bb);
            }
        }
    };

    ldg_tile(0); sts_tile(0); __syncthreads();
    const int KIT = K2 / BK;
    for (int kb = 0; kb < KIT; kb++) {
        const int s = kb & 1;
        if (kb + 1 < KIT) ldg_tile(kb + 1);
        compute(s);
        if (kb + 1 < KIT) { __syncthreads(); sts_tile(s ^ 1); __syncthreads(); }
    }

    #pragma unroll
    for (int mi = 0; mi < 2; mi++)
        #pragma unroll
        for (int ni = 0; ni < 4; ni++) {
            const int r = mt * BM + wm * 32 + mi * 16 + lg;
            const int c = nt * BN + wn * 32 + ni * 8 + lt * 2;
            #pragma unroll
            for (int half = 0; half < 2; half++) {
                const int rr = r + half * 8;
                *(float2*)(g_xmcmp + (size_t)rr * C_ + c) =
                    make_float2(siluf(acc[mi][ni][half * 2]),
                                siluf(acc[mi][ni][half * 2 + 1]));
            }
        }
}

// ---------------- interleave ----------------
__global__ __launch_bounds__(256)
void interleave_kernel(const float* __restrict__ x_m, float* __restrict__ out) {
    const int b = blockIdx.y, i = blockIdx.x, tid = threadIdx.x;
    if (i < TCMP) {
        const int dst = g_keepdst[b * TCMP + i];
        if (dst < 0) return;
        const float4* s = (const float4*)(g_xmcmp + ((size_t)(b * TCMP + i)) * C_);
        float4* d = (float4*)(out + ((size_t)(b * OUTLEN + dst)) * C_);
        for (int j = tid; j < C_ / 4; j += 256) d[j] = s[j];
    } else {
        const int k = i - TCMP;
        const int sk  = g_seqsel[b * NSEL + k];
        const int pos = sk + k;
        const int src = g_seldesc[b * NSEL + k];
        const float4* s = (const float4*)(x_m + ((size_t)(b * 2 * TCMP) + 2 * src) * C_);
        float4* d = (float4*)(out + ((size_t)(b * OUTLEN + pos)) * C_);
        for (int j = tid; j < 2 * C_ / 4; j += 256) d[j] = s[j];
    }
}

// ---------------- launch ----------------
extern "C" void kernel_launch(void* const* d_in, const int* in_sizes, int n_in,
                              void* d_out, int out_size) {
    const float* x_m = (const float*)d_in[0];
    const float* q_w = (const float*)d_in[1];
    const float* km  = (const float*)d_in[2];
    const float* Wg  = (const float*)d_in[3];
    const float* Wu  = (const float*)d_in[4];
    const float* Wd  = (const float*)d_in[5];
    float* out = (float*)d_out;

    cudaFuncSetAttribute(importance_kernel,
                         cudaFuncAttributeMaxDynamicSharedMemorySize, IMP_SMEM);

    importance_kernel<<<dim3(TW / IQ, B_ * H_), 256, IMP_SMEM>>>(q_w, km);
    reduce_imp_kernel<<<(B_ * TCMP + 255) / 256, 256>>>();
    topk_kernel<<<B_, 1024>>>();
    gemm1_kernel<<<2048, 256>>>(x_m, Wg, Wu);
    gemm2_kernel<<<2048, 256>>>(Wd);
    interleave_kernel<<<dim3(TCMP + NSEL, B_), 256>>>(x_m, out);
}

// round 13
// speedup vs baseline: 1.6824x; 1.2490x over previous
#include <cuda_runtime.h>
#include <cstdint>
#include <cstddef>

#define B_      4
#define TCMP    2048
#define C_      2048
#define H_      16
#define KV_     8
#define TW      1024
#define D_      128
#define NSEL    512
#define OUTLEN  2560
#define M_      (B_*TCMP)
#define K1      (2*C_)
#define K2      2048
#define SCALE_F 0.08838834764831845f

__device__ float  g_h[(size_t)M_ * C_];
__device__ float  g_xmcmp[(size_t)M_ * C_];
__device__ float  g_w[(size_t)B_ * H_ * TW * TCMP];   // 512 MB softmax weights
__device__ float  g_part[B_ * H_ * TCMP];
__device__ float  g_imp[B_ * TCMP];
__device__ int    g_seldesc[B_ * NSEL];
__device__ int    g_seqsel[B_ * NSEL];
__device__ int    g_keepdst[B_ * TCMP];

__device__ __forceinline__ float siluf(float x) { return x / (1.f + expf(-x)); }
__device__ __forceinline__ uint32_t f2tf(float x) {
    uint32_t u; asm("cvt.rna.tf32.f32 %0, %1;" : "=r"(u) : "f"(x)); return u;
}
__device__ __forceinline__ float tf32r(float x) {
    return __uint_as_float(f2tf(x));
}
__device__ __forceinline__ void mma8(float* c, const uint32_t* a, const uint32_t* b) {
    asm volatile("mma.sync.aligned.m16n8k8.row.col.f32.tf32.tf32.f32 "
                 "{%0,%1,%2,%3}, {%4,%5,%6,%7}, {%8,%9}, {%0,%1,%2,%3};"
                 : "+f"(c[0]), "+f"(c[1]), "+f"(c[2]), "+f"(c[3])
                 : "r"(a[0]), "r"(a[1]), "r"(a[2]), "r"(a[3]), "r"(b[0]), "r"(b[1]));
}

// ---------------- importance pass 1 (FROZEN numerics) ----------------
#define IQ   16
#define KT   512
#define DC   32
#define QS_OFF   (IQ*TCMP)
#define KMS_OFF  (QS_OFF + IQ*D_)
#define IVZ_OFF  (KMS_OFF + KT*33)
#define IMP_SMEM ((IVZ_OFF + IQ) * 4)

__global__ __launch_bounds__(256, 1)
void importance_kernel(const float* __restrict__ q_w, const float* __restrict__ km) {
    extern __shared__ float sm[];
    const int tid = threadIdx.x;
    const int bh = blockIdx.y;
    const int b = bh >> 4, h = bh & 15;
    const int qbase = blockIdx.x * IQ;
    const float* qp = q_w + (((size_t)(b * H_ + h)) * TW + qbase) * D_;
    const float* kp = km + ((size_t)(b * KV_ + (h >> 1))) * TCMP * D_;

    for (int i = tid; i < IQ * D_ / 4; i += 256)
        ((float4*)(sm + QS_OFF))[i] = ((const float4*)qp)[i];

    const int qg = tid >> 6, kg = tid & 63;
    float* sc  = sm;
    float* kms = sm + KMS_OFF;

    for (int kt = 0; kt < TCMP / KT; kt++) {
        float acc[4][8];
        #pragma unroll
        for (int qi = 0; qi < 4; qi++)
            #pragma unroll
            for (int j = 0; j < 8; j++) acc[qi][j] = 0.f;

        for (int dc = 0; dc < D_ / DC; dc++) {
            __syncthreads();
            for (int r = tid; r < KT; r += 256) {
                const float* src = kp + (size_t)(kt * KT + r) * D_ + dc * DC;
                #pragma unroll
                for (int f = 0; f < DC / 4; f++) {
                    float4 v = ((const float4*)src)[f];
                    float* d = kms + r * 33 + f * 4;
                    d[0] = v.x; d[1] = v.y; d[2] = v.z; d[3] = v.w;
                }
            }
            __syncthreads();
            #pragma unroll
            for (int d = 0; d < DC; d++) {
                float qv[4];
                #pragma unroll
                for (int qi = 0; qi < 4; qi++)
                    qv[qi] = sm[QS_OFF + (qg * 4 + qi) * D_ + dc * DC + d];
                #pragma unroll
                for (int j = 0; j < 8; j++) {
                    float kv = kms[(j * 64 + kg) * 33 + d];
                    #pragma unroll
                    for (int qi = 0; qi < 4; qi++) acc[qi][j] += qv[qi] * kv;
                }
            }
        }
        #pragma unroll
        for (int qi = 0; qi < 4; qi++)
            #pragma unroll
            for (int j = 0; j < 8; j++)
                sc[(qg * 4 + qi) * TCMP + kt * KT + j * 64 + kg] = acc[qi][j];
    }
    __syncthreads();

    const int warp = tid >> 5, lane = tid & 31;
    for (int r = warp; r < IQ; r += 8) {
        float m = -1e30f;
        for (int i = lane; i < TCMP; i += 32) {
            float t = sc[r * TCMP + i] * SCALE_F;
            sc[r * TCMP + i] = t;
            m = fmaxf(m, t);
        }
        #pragma unroll
        for (int o = 16; o; o >>= 1) m = fmaxf(m, __shfl_xor_sync(~0u, m, o));
        float z = 0.f;
        for (int i = lane; i < TCMP; i += 32) {
            float e = expf(sc[r * TCMP + i] - m);
            sc[r * TCMP + i] = e;
            z += e;
        }
        #pragma unroll
        for (int o = 16; o; o >>= 1) z += __shfl_xor_sync(~0u, z, o);
        if (lane == 0) sm[IVZ_OFF + r] = z;
    }
    __syncthreads();

    float* wp = g_w + ((size_t)bh * TW + qbase) * TCMP;
    for (int idx = tid; idx < IQ * TCMP; idx += 256) {
        const int r = idx >> 11, k = idx & (TCMP - 1);
        wp[(size_t)r * TCMP + k] = sc[r * TCMP + k] / sm[IVZ_OFF + r];
    }
}

// ------- reduce: bit-identical to frozen order, parallelized per (b,h) -------
__global__ __launch_bounds__(256)
void reduce_h_kernel() {
    const int i = blockIdx.x * blockDim.x + threadIdx.x;   // B_*H_*TCMP = 131072
    if (i >= B_ * H_ * TCMP) return;
    const int k = i & (TCMP - 1);
    const int h = (i >> 11) & 15;
    const int b = i >> 15;
    const float* p = g_w + ((size_t)(b * H_ + h) * TW) * TCMP + k;
    float part[32];
    #pragma unroll
    for (int j = 0; j < 32; j++) part[j] = 0.f;
    for (int ii = 0; ii < 32; ii++) {
        #pragma unroll
        for (int j = 0; j < 32; j++)
            part[j] += p[(size_t)(j + 32 * ii) * TCMP];
    }
    #pragma unroll
    for (int off = 16; off >= 1; off >>= 1)
        #pragma unroll
        for (int j = 0; j < 16; j++)
            if (j < off) part[j] = part[j] + part[j + off];
    g_part[i] = part[0];
}

__global__ __launch_bounds__(256)
void reduce_final_kernel() {
    const int i = blockIdx.x * blockDim.x + threadIdx.x;   // 8192
    if (i >= B_ * TCMP) return;
    const int b = i >> 11, k = i & (TCMP - 1);
    float S[16];
    #pragma unroll
    for (int h = 0; h < 16; h++) S[h] = g_part[(b * 16 + h) * TCMP + k];
    #pragma unroll
    for (int off = 8; off >= 1; off >>= 1)
        #pragma unroll
        for (int j = 0; j < 8; j++)
            if (j < off) S[j] = S[j] + S[j + off];
    g_imp[i] = S[0] / 16.f;
}

// ---------------- top-k (FROZEN) ----------------
__global__ __launch_bounds__(1024)
void topk_kernel() {
    __shared__ float v[TCMP];
    __shared__ int rnk[TCMP];
    __shared__ int selm[TCMP];
    const int b = blockIdx.x, tid = threadIdx.x;
    for (int i = tid; i < TCMP; i += 1024) v[i] = g_imp[b * TCMP + i];
    __syncthreads();
    for (int t = tid; t < TCMP; t += 1024) {
        float x = v[t];
        int r = 0;
        for (int j = 0; j < TCMP; j++) {
            float y = v[j];
            r += (y > x) || (y == x && j < t);
        }
        rnk[t] = r;
    }
    __syncthreads();
    for (int t = tid; t < TCMP; t += 1024) selm[t] = rnk[t] < NSEL;
    __syncthreads();
    for (int t = tid; t < TCMP; t += 1024) {
        int cb = 0;
        for (int j = 0; j < t; j++) cb += selm[j];
        if (selm[t]) {
            g_seldesc[b * NSEL + rnk[t]] = t;
            g_seqsel[b * NSEL + cb] = t;
            g_keepdst[b * TCMP + t] = -1;
        } else {
            g_keepdst[b * TCMP + t] = t + cb;
        }
    }
}

// ---------------- GEMM 1: fused gate/up, 1xTF32, cvt hoisted to STS ----------------
#define BM 128
#define BN 64
#define BK 16

__global__ __launch_bounds__(256, 2)
void gemm1_kernel(const float* __restrict__ X,
                  const float* __restrict__ Wg, const float* __restrict__ Wu) {
    __shared__ float As[2][BK][BM + 4];
    __shared__ float Bs[2][2][BK][BN + 4];
    const int tid = threadIdx.x, bid = blockIdx.x;
    const int mt = (bid >> 9) * 16 + (bid & 15);
    const int nt = (bid >> 4) & 31;
    const float* Ap  = X  + (size_t)mt * BM * K1;
    const float* Bgp = Wg + (size_t)nt * BN * K1;
    const float* Bup = Wu + (size_t)nt * BN * K1;
    const int warp = tid >> 5, lane = tid & 31;
    const int wm = warp & 3, wn = warp >> 2;
    const int lt = lane & 3, lg = lane >> 2;

    float accG[2][4][4], accU[2][4][4];
    #pragma unroll
    for (int a = 0; a < 2; a++)
        #pragma unroll
        for (int b2 = 0; b2 < 4; b2++)
            #pragma unroll
            for (int c = 0; c < 4; c++) { accG[a][b2][c] = 0.f; accU[a][b2][c] = 0.f; }

    float4 ra0, ra1, rg, ru;
    const int lrow = tid >> 2, lc0 = (tid & 3) * 4;

    auto ldg_tile = [&](int kb) {
        const float* a = Ap + kb * BK;
        ra0 = *(const float4*)(a + (size_t)lrow * K1 + lc0);
        ra1 = *(const float4*)(a + (size_t)(lrow + 64) * K1 + lc0);
        rg  = *(const float4*)(Bgp + kb * BK + (size_t)lrow * K1 + lc0);
        ru  = *(const float4*)(Bup + kb * BK + (size_t)lrow * K1 + lc0);
    };
    // store tf32-rounded values: mma later consumes bits directly (idempotent rounding)
    auto sts_tile = [&](int s) {
        const float *p0 = (const float*)&ra0, *p1 = (const float*)&ra1;
        const float *pg = (const float*)&rg,  *pu = (const float*)&ru;
        #pragma unroll
        for (int j = 0; j < 4; j++) {
            As[s][lc0 + j][lrow]      = tf32r(p0[j]);
            As[s][lc0 + j][lrow + 64] = tf32r(p1[j]);
            Bs[s][0][lc0 + j][lrow]   = tf32r(pg[j]);
            Bs[s][1][lc0 + j][lrow]   = tf32r(pu[j]);
        }
    };
    auto compute = [&](int s) {
        #pragma unroll
        for (int ks = 0; ks < 2; ks++) {
            const int k0 = ks * 8;
            uint32_t a[2][4];
            #pragma unroll
            for (int mi = 0; mi < 2; mi++) {
                const int mb = wm * 32 + mi * 16;
                a[mi][0] = __float_as_uint(As[s][k0 + lt][mb + lg]);
                a[mi][1] = __float_as_uint(As[s][k0 + lt][mb + lg + 8]);
                a[mi][2] = __float_as_uint(As[s][k0 + 4 + lt][mb + lg]);
                a[mi][3] = __float_as_uint(As[s][k0 + 4 + lt][mb + lg + 8]);
            }
            #pragma unroll
            for (int ni = 0; ni < 4; ni++) {
                const int nb = wn * 32 + ni * 8;
                uint32_t bg[2], bu[2];
                bg[0] = __float_as_uint(Bs[s][0][k0 + lt][nb + lg]);
                bg[1] = __float_as_uint(Bs[s][0][k0 + 4 + lt][nb + lg]);
                bu[0] = __float_as_uint(Bs[s][1][k0 + lt][nb + lg]);
                bu[1] = __float_as_uint(Bs[s][1][k0 + 4 + lt][nb + lg]);
                #pragma unroll
                for (int mi = 0; mi < 2; mi++) {
                    mma8(accG[mi][ni], a[mi], bg);
                    mma8(accU[mi][ni], a[mi], bu);
                }
            }
        }
    };

    ldg_tile(0); sts_tile(0); __syncthreads();
    const int KIT = K1 / BK;
    for (int kb = 0; kb < KIT; kb++) {
        const int s = kb & 1;
        if (kb + 1 < KIT) ldg_tile(kb + 1);
        compute(s);
        if (kb + 1 < KIT) { __syncthreads(); sts_tile(s ^ 1); __syncthreads(); }
    }

    #pragma unroll
    for (int mi = 0; mi < 2; mi++)
        #pragma unroll
        for (int ni = 0; ni < 4; ni++) {
            const int r = mt * BM + wm * 32 + mi * 16 + lg;
            const int c = nt * BN + wn * 32 + ni * 8 + lt * 2;
            #pragma unroll
            for (int half = 0; half < 2; half++) {
                const int rr = r + half * 8;
                float g0 = accG[mi][ni][half * 2], g1 = accG[mi][ni][half * 2 + 1];
                float u0 = accU[mi][ni][half * 2], u1 = accU[mi][ni][half * 2 + 1];
                *(float2*)(g_h + (size_t)rr * C_ + c) =
                    make_float2(siluf(g0) * u0, siluf(g1) * u1);
            }
        }
}

// ---------------- GEMM 2: down-proj, 1xTF32, cvt hoisted to STS ----------------
__global__ __launch_bounds__(256, 2)
void gemm2_kernel(const float* __restrict__ Wd) {
    __shared__ float As[2][BK][BM + 4];
    __shared__ float Bs[2][BK][BN + 4];
    const int tid = threadIdx.x, bid = blockIdx.x;
    const int nt = bid & 31, mt = bid >> 5;
    const float* Ap = g_h + (size_t)mt * BM * K2;
    const float* Bp = Wd  + (size_t)nt * BN * K2;
    const int warp = tid >> 5, lane = tid & 31;
    const int wm = warp & 3, wn = warp >> 2;
    const int lt = lane & 3, lg = lane >> 2;

    float acc[2][4][4];
    #pragma unroll
    for (int a = 0; a < 2; a++)
        #pragma unroll
        for (int b2 = 0; b2 < 4; b2++)
            #pragma unroll
            for (int c = 0; c < 4; c++) acc[a][b2][c] = 0.f;

    float4 ra0, ra1, rb;
    const int lrow = tid >> 2, lc0 = (tid & 3) * 4;

    auto ldg_tile = [&](int kb) {
        const float* a = Ap + kb * BK;
        ra0 = *(const float4*)(a + (size_t)lrow * K2 + lc0);
        ra1 = *(const float4*)(a + (size_t)(lrow + 64) * K2 + lc0);
        rb  = *(const float4*)(Bp + kb * BK + (size_t)lrow * K2 + lc0);
    };
    auto sts_tile = [&](int s) {
        const float *p0 = (const float*)&ra0, *p1 = (const float*)&ra1;
        const float *pb = (const float*)&rb;
        #pragma unroll
        for (int j = 0; j < 4; j++) {
            As[s][lc0 + j][lrow]      = tf32r(p0[j]);
            As[s][lc0 + j][lrow + 64] = tf32r(p1[j]);
            Bs[s][lc0 + j][lrow]      = tf32r(pb[j]);
        }
    };
    auto compute = [&](int s) {
        #pragma unroll
        for (int ks = 0; ks < 2; ks++) {
            const int k0 = ks * 8;
            uint32_t a[2][4];
            #pragma unroll
            for (int mi = 0; mi < 2; mi++) {
                const int mb = wm * 32 + mi * 16;
                a[mi][0] = __float_as_uint(As[s][k0 + lt][mb + lg]);
                a[mi][1] = __float_as_uint(As[s][k0 + lt][mb + lg + 8]);
                a[mi][2] = __float_as_uint(As[s][k0 + 4 + lt][mb + lg]);
                a[mi][3] = __float_as_uint(As[s][k0 + 4 + lt][mb + lg + 8]);
            }
            #pragma unroll
            for (int ni = 0; ni < 4; ni++) {
                const int nb = wn * 32 + ni * 8;
                uint32_t bb[2];
                bb[0] = __float_as_uint(Bs[s][k0 + lt][nb + lg]);
                bb[1] = __float_as_uint(Bs[s][k0 + 4 + lt][nb + lg]);
                #pragma unroll
                for (int mi = 0; mi < 2; mi++) mma8(acc[mi][ni], a[mi], bb);
            }
        }
    };

    ldg_tile(0); sts_tile(0); __syncthreads();
    const int KIT = K2 / BK;
    for (int kb = 0; kb < KIT; kb++) {
        const int s = kb & 1;
        if (kb + 1 < KIT) ldg_tile(kb + 1);
        compute(s);
        if (kb + 1 < KIT) { __syncthreads(); sts_tile(s ^ 1); __syncthreads(); }
    }

    #pragma unroll
    for (int mi = 0; mi < 2; mi++)
        #pragma unroll
        for (int ni = 0; ni < 4; ni++) {
            const int r = mt * BM + wm * 32 + mi * 16 + lg;
            const int c = nt * BN + wn * 32 + ni * 8 + lt * 2;
            #pragma unroll
            for (int half = 0; half < 2; half++) {
                const int rr = r + half * 8;
                *(float2*)(g_xmcmp + (size_t)rr * C_ + c) =
                    make_float2(siluf(acc[mi][ni][half * 2]),
                                siluf(acc[mi][ni][half * 2 + 1]));
            }
        }
}

// ---------------- interleave (FROZEN) ----------------
__global__ __launch_bounds__(256)
void interleave_kernel(const float* __restrict__ x_m, float* __restrict__ out) {
    const int b = blockIdx.y, i = blockIdx.x, tid = threadIdx.x;
    if (i < TCMP) {
        const int dst = g_keepdst[b * TCMP + i];
        if (dst < 0) return;
        const float4* s = (const float4*)(g_xmcmp + ((size_t)(b * TCMP + i)) * C_);
        float4* d = (float4*)(out + ((size_t)(b * OUTLEN + dst)) * C_);
        for (int j = tid; j < C_ / 4; j += 256) d[j] = s[j];
    } else {
        const int k = i - TCMP;
        const int sk  = g_seqsel[b * NSEL + k];
        const int pos = sk + k;
        const int src = g_seldesc[b * NSEL + k];
        const float4* s = (const float4*)(x_m + ((size_t)(b * 2 * TCMP) + 2 * src) * C_);
        float4* d = (float4*)(out + ((size_t)(b * OUTLEN + pos)) * C_);
        for (int j = tid; j < 2 * C_ / 4; j += 256) d[j] = s[j];
    }
}

// ---------------- launch ----------------
extern "C" void kernel_launch(void* const* d_in, const int* in_sizes, int n_in,
                              void* d_out, int out_size) {
    const float* x_m = (const float*)d_in[0];
    const float* q_w = (const float*)d_in[1];
    const float* km  = (const float*)d_in[2];
    const float* Wg  = (const float*)d_in[3];
    const float* Wu  = (const float*)d_in[4];
    const float* Wd  = (const float*)d_in[5];
    float* out = (float*)d_out;

    cudaFuncSetAttribute(importance_kernel,
                         cudaFuncAttributeMaxDynamicSharedMemorySize, IMP_SMEM);

    importance_kernel<<<dim3(TW / IQ, B_ * H_), 256, IMP_SMEM>>>(q_w, km);
    reduce_h_kernel<<<(B_ * H_ * TCMP + 255) / 256, 256>>>();
    reduce_final_kernel<<<(B_ * TCMP + 255) / 256, 256>>>();
    topk_kernel<<<B_, 1024>>>();
    gemm1_kernel<<<2048, 256>>>(x_m, Wg, Wu);
    gemm2_kernel<<<2048, 256>>>(Wd);
    interleave_kernel<<<dim3(TCMP + NSEL, B_), 256>>>(x_m, out);
}

// round 15
// speedup vs baseline: 1.7145x; 1.0191x over previous
#include <cuda_runtime.h>
#include <cstdint>
#include <cstddef>

#define B_      4
#define TCMP    2048
#define C_      2048
#define H_      16
#define KV_     8
#define TW      1024
#define D_      128
#define NSEL    512
#define OUTLEN  2560
#define M_      (B_*TCMP)
#define K1      (2*C_)
#define K2      2048
#define SCALE_F 0.08838834764831845f

__device__ float  g_h[(size_t)M_ * C_];
__device__ float  g_xmcmp[(size_t)M_ * C_];
__device__ float  g_w[(size_t)B_ * H_ * TW * TCMP];   // 512 MB softmax weights
__device__ float  g_part[B_ * H_ * TCMP];
__device__ float  g_imp[B_ * TCMP];
__device__ int    g_rnk[B_ * TCMP];
__device__ int    g_seldesc[B_ * NSEL];
__device__ int    g_seqsel[B_ * NSEL];
__device__ int    g_keepdst[B_ * TCMP];

__device__ __forceinline__ float siluf(float x) { return x / (1.f + expf(-x)); }
__device__ __forceinline__ uint32_t f2tf(float x) {
    uint32_t u; asm("cvt.rna.tf32.f32 %0, %1;" : "=r"(u) : "f"(x)); return u;
}
__device__ __forceinline__ float tf32r(float x) {
    return __uint_as_float(f2tf(x));
}
__device__ __forceinline__ void mma8(float* c, const uint32_t* a, const uint32_t* b) {
    asm volatile("mma.sync.aligned.m16n8k8.row.col.f32.tf32.tf32.f32 "
                 "{%0,%1,%2,%3}, {%4,%5,%6,%7}, {%8,%9}, {%0,%1,%2,%3};"
                 : "+f"(c[0]), "+f"(c[1]), "+f"(c[2]), "+f"(c[3])
                 : "r"(a[0]), "r"(a[1]), "r"(a[2]), "r"(a[3]), "r"(b[0]), "r"(b[1]));
}

// ---------------- importance pass 1 (FROZEN numerics; 512 threads) ----------------
// Per-score FFMA chain order (ascending d, dc chunks) and per-row softmax
// lane/tree order are preserved exactly -> bit-identical to the R13 pass.
#define IQ   16
#define KT   512
#define DC   32
#define QS_OFF   (IQ*TCMP)
#define KMS_OFF  (QS_OFF + IQ*D_)
#define IVZ_OFF  (KMS_OFF + KT*33)
#define IMP_SMEM ((IVZ_OFF + IQ) * 4)

__global__ __launch_bounds__(512, 1)
void importance_kernel(const float* __restrict__ q_w, const float* __restrict__ km) {
    extern __shared__ float sm[];
    const int tid = threadIdx.x;
    const int bh = blockIdx.y;
    const int b = bh >> 4, h = bh & 15;
    const int qbase = blockIdx.x * IQ;
    const float* qp = q_w + (((size_t)(b * H_ + h)) * TW + qbase) * D_;
    const float* kp = km + ((size_t)(b * KV_ + (h >> 1))) * TCMP * D_;

    for (int i = tid; i < IQ * D_ / 4; i += 512)
        ((float4*)(sm + QS_OFF))[i] = ((const float4*)qp)[i];

    const int qg = tid >> 7;       // 0..3  (4 q rows each)
    const int kg = tid & 127;      // 0..127 (4 k cols each, strided 128)
    float* sc  = sm;
    float* kms = sm + KMS_OFF;

    for (int kt = 0; kt < TCMP / KT; kt++) {
        float acc[4][4];
        #pragma unroll
        for (int qi = 0; qi < 4; qi++)
            #pragma unroll
            for (int j = 0; j < 4; j++) acc[qi][j] = 0.f;

        for (int dc = 0; dc < D_ / DC; dc++) {
            __syncthreads();
            for (int r = tid; r < KT; r += 512) {
                const float* src = kp + (size_t)(kt * KT + r) * D_ + dc * DC;
                #pragma unroll
                for (int f = 0; f < DC / 4; f++) {
                    float4 v = ((const float4*)src)[f];
                    float* d = kms + r * 33 + f * 4;
                    d[0] = v.x; d[1] = v.y; d[2] = v.z; d[3] = v.w;
                }
            }
            __syncthreads();
            #pragma unroll
            for (int d = 0; d < DC; d++) {
                float qv[4];
                #pragma unroll
                for (int qi = 0; qi < 4; qi++)
                    qv[qi] = sm[QS_OFF + (qg * 4 + qi) * D_ + dc * DC + d];
                #pragma unroll
                for (int j = 0; j < 4; j++) {
                    float kv = kms[(j * 128 + kg) * 33 + d];
                    #pragma unroll
                    for (int qi = 0; qi < 4; qi++) acc[qi][j] += qv[qi] * kv;
                }
            }
        }
        #pragma unroll
        for (int qi = 0; qi < 4; qi++)
            #pragma unroll
            for (int j = 0; j < 4; j++)
                sc[(qg * 4 + qi) * TCMP + kt * KT + j * 128 + kg] = acc[qi][j];
    }
    __syncthreads();

    const int warp = tid >> 5, lane = tid & 31;
    if (warp < IQ) {
        const int r = warp;   // one row per warp; identical lane/tree pattern per row
        float m = -1e30f;
        for (int i = lane; i < TCMP; i += 32) {
            float t = sc[r * TCMP + i] * SCALE_F;
            sc[r * TCMP + i] = t;
            m = fmaxf(m, t);
        }
        #pragma unroll
        for (int o = 16; o; o >>= 1) m = fmaxf(m, __shfl_xor_sync(~0u, m, o));
        float z = 0.f;
        for (int i = lane; i < TCMP; i += 32) {
            float e = expf(sc[r * TCMP + i] - m);
            sc[r * TCMP + i] = e;
            z += e;
        }
        #pragma unroll
        for (int o = 16; o; o >>= 1) z += __shfl_xor_sync(~0u, z, o);
        if (lane == 0) sm[IVZ_OFF + r] = z;
    }
    __syncthreads();

    float* wp = g_w + ((size_t)bh * TW + qbase) * TCMP;
    for (int idx = tid; idx < IQ * TCMP; idx += 512) {
        const int r = idx >> 11, k = idx & (TCMP - 1);
        wp[(size_t)r * TCMP + k] = sc[r * TCMP + k] / sm[IVZ_OFF + r];
    }
}

// ------- reduce: bit-identical to frozen order, parallelized per (b,h) -------
__global__ __launch_bounds__(256)
void reduce_h_kernel() {
    const int i = blockIdx.x * blockDim.x + threadIdx.x;   // B_*H_*TCMP = 131072
    if (i >= B_ * H_ * TCMP) return;
    const int k = i & (TCMP - 1);
    const int h = (i >> 11) & 15;
    const int b = i >> 15;
    const float* p = g_w + ((size_t)(b * H_ + h) * TW) * TCMP + k;
    float part[32];
    #pragma unroll
    for (int j = 0; j < 32; j++) part[j] = 0.f;
    for (int ii = 0; ii < 32; ii++) {
        #pragma unroll
        for (int j = 0; j < 32; j++)
            part[j] += p[(size_t)(j + 32 * ii) * TCMP];
    }
    #pragma unroll
    for (int off = 16; off >= 1; off >>= 1)
        #pragma unroll
        for (int j = 0; j < 16; j++)
            if (j < off) part[j] = part[j] + part[j + off];
    g_part[i] = part[0];
}

__global__ __launch_bounds__(256)
void reduce_final_kernel() {
    const int i = blockIdx.x * blockDim.x + threadIdx.x;   // 8192
    if (i >= B_ * TCMP) return;
    const int b = i >> 11, k = i & (TCMP - 1);
    float S[16];
    #pragma unroll
    for (int h = 0; h < 16; h++) S[h] = g_part[(b * 16 + h) * TCMP + k];
    #pragma unroll
    for (int off = 8; off >= 1; off >>= 1)
        #pragma unroll
        for (int j = 0; j < 8; j++)
            if (j < off) S[j] = S[j] + S[j + off];
    g_imp[i] = S[0] / 16.f;
}

// ---------------- top-k: rank phase (parallel) + finalize (FROZEN semantics) ----------
__global__ __launch_bounds__(256)
void rank_kernel() {
    __shared__ float v[TCMP];
    const int b = blockIdx.x, seg = blockIdx.y, tid = threadIdx.x;
    for (int i = tid; i < TCMP; i += 256) v[i] = g_imp[b * TCMP + i];
    __syncthreads();
    const int t = seg * 256 + tid;
    float x = v[t];
    int r = 0;
    for (int j = 0; j < TCMP; j++) {
        float y = v[j];
        r += (y > x) || (y == x && j < t);
    }
    g_rnk[b * TCMP + t] = r;
}

__global__ __launch_bounds__(1024)
void topk_finalize_kernel() {
    __shared__ int rnk[TCMP];
    __shared__ int selm[TCMP];
    const int b = blockIdx.x, tid = threadIdx.x;
    for (int i = tid; i < TCMP; i += 1024) {
        rnk[i] = g_rnk[b * TCMP + i];
        selm[i] = (rnk[i] < NSEL);
    }
    __syncthreads();
    for (int t = tid; t < TCMP; t += 1024) {
        int cb = 0;
        for (int j = 0; j < t; j++) cb += selm[j];
        if (selm[t]) {
            g_seldesc[b * NSEL + rnk[t]] = t;
            g_seqsel[b * NSEL + cb] = t;
            g_keepdst[b * TCMP + t] = -1;
        } else {
            g_keepdst[b * TCMP + t] = t + cb;
        }
    }
}

// ---------------- GEMM 1: fused gate/up, 1xTF32, cvt at STS, single-sync pipe --------
#define BM 128
#define BN 64
#define BK 16

__global__ __launch_bounds__(256, 2)
void gemm1_kernel(const float* __restrict__ X,
                  const float* __restrict__ Wg, const float* __restrict__ Wu) {
    __shared__ float As[2][BK][BM + 4];
    __shared__ float Bs[2][2][BK][BN + 4];
    const int tid = threadIdx.x, bid = blockIdx.x;
    const int mt = (bid >> 9) * 16 + (bid & 15);
    const int nt = (bid >> 4) & 31;
    const float* Ap  = X  + (size_t)mt * BM * K1;
    const float* Bgp = Wg + (size_t)nt * BN * K1;
    const float* Bup = Wu + (size_t)nt * BN * K1;
    const int warp = tid >> 5, lane = tid & 31;
    const int wm = warp & 3, wn = warp >> 2;
    const int lt = lane & 3, lg = lane >> 2;

    float accG[2][4][4], accU[2][4][4];
    #pragma unroll
    for (int a = 0; a < 2; a++)
        #pragma unroll
        for (int b2 = 0; b2 < 4; b2++)
            #pragma unroll
            for (int c = 0; c < 4; c++) { accG[a][b2][c] = 0.f; accU[a][b2][c] = 0.f; }

    float4 ra0, ra1, rg, ru;
    const int lrow = tid >> 2, lc0 = (tid & 3) * 4;

    auto ldg_tile = [&](int kb) {
        const float* a = Ap + kb * BK;
        ra0 = *(const float4*)(a + (size_t)lrow * K1 + lc0);
        ra1 = *(const float4*)(a + (size_t)(lrow + 64) * K1 + lc0);
        rg  = *(const float4*)(Bgp + kb * BK + (size_t)lrow * K1 + lc0);
        ru  = *(const float4*)(Bup + kb * BK + (size_t)lrow * K1 + lc0);
    };
    auto sts_tile = [&](int s) {
        const float *p0 = (const float*)&ra0, *p1 = (const float*)&ra1;
        const float *pg = (const float*)&rg,  *pu = (const float*)&ru;
        #pragma unroll
        for (int j = 0; j < 4; j++) {
            As[s][lc0 + j][lrow]      = tf32r(p0[j]);
            As[s][lc0 + j][lrow + 64] = tf32r(p1[j]);
            Bs[s][0][lc0 + j][lrow]   = tf32r(pg[j]);
            Bs[s][1][lc0 + j][lrow]   = tf32r(pu[j]);
        }
    };
    auto compute = [&](int s) {
        #pragma unroll
        for (int ks = 0; ks < 2; ks++) {
            const int k0 = ks * 8;
            uint32_t a[2][4];
            #pragma unroll
            for (int mi = 0; mi < 2; mi++) {
                const int mb = wm * 32 + mi * 16;
                a[mi][0] = __float_as_uint(As[s][k0 + lt][mb + lg]);
                a[mi][1] = __float_as_uint(As[s][k0 + lt][mb + lg + 8]);
                a[mi][2] = __float_as_uint(As[s][k0 + 4 + lt][mb + lg]);
                a[mi][3] = __float_as_uint(As[s][k0 + 4 + lt][mb + lg + 8]);
            }
            #pragma unroll
            for (int ni = 0; ni < 4; ni++) {
                const int nb = wn * 32 + ni * 8;
                uint32_t bg[2], bu[2];
                bg[0] = __float_as_uint(Bs[s][0][k0 + lt][nb + lg]);
                bg[1] = __float_as_uint(Bs[s][0][k0 + 4 + lt][nb + lg]);
                bu[0] = __float_as_uint(Bs[s][1][k0 + lt][nb + lg]);
                bu[1] = __float_as_uint(Bs[s][1][k0 + 4 + lt][nb + lg]);
                #pragma unroll
                for (int mi = 0; mi < 2; mi++) {
                    mma8(accG[mi][ni], a[mi], bg);
                    mma8(accU[mi][ni], a[mi], bu);
                }
            }
        }
    };

    ldg_tile(0); sts_tile(0); __syncthreads();
    const int KIT = K1 / BK;
    for (int kb = 0; kb < KIT; kb++) {
        const int s = kb & 1;
        if (kb + 1 < KIT) ldg_tile(kb + 1);
        compute(s);
        // single barrier: sts(s^1) hazard vs compute(s^1)@kb-1 was covered by the
        // barrier at end of kb-1; next read of s^1 is after this barrier.
        if (kb + 1 < KIT) { sts_tile(s ^ 1); __syncthreads(); }
    }

    #pragma unroll
    for (int mi = 0; mi < 2; mi++)
        #pragma unroll
        for (int ni = 0; ni < 4; ni++) {
            const int r = mt * BM + wm * 32 + mi * 16 + lg;
            const int c = nt * BN + wn * 32 + ni * 8 + lt * 2;
            #pragma unroll
            for (int half = 0; half < 2; half++) {
                const int rr = r + half * 8;
                float g0 = accG[mi][ni][half * 2], g1 = accG[mi][ni][half * 2 + 1];
                float u0 = accU[mi][ni][half * 2], u1 = accU[mi][ni][half * 2 + 1];
                *(float2*)(g_h + (size_t)rr * C_ + c) =
                    make_float2(siluf(g0) * u0, siluf(g1) * u1);
            }
        }
}

// ---------------- GEMM 2: down-proj, 1xTF32, cvt at STS, single-sync pipe ----------
__global__ __launch_bounds__(256, 2)
void gemm2_kernel(const float* __restrict__ Wd) {
    __shared__ float As[2][BK][BM + 4];
    __shared__ float Bs[2][BK][BN + 4];
    const int tid = threadIdx.x, bid = blockIdx.x;
    const int nt = bid & 31, mt = bid >> 5;
    const float* Ap = g_h + (size_t)mt * BM * K2;
    const float* Bp = Wd  + (size_t)nt * BN * K2;
    const int warp = tid >> 5, lane = tid & 31;
    const int wm = warp & 3, wn = warp >> 2;
    const int lt = lane & 3, lg = lane >> 2;

    float acc[2][4][4];
    #pragma unroll
    for (int a = 0; a < 2; a++)
        #pragma unroll
        for (int b2 = 0; b2 < 4; b2++)
            #pragma unroll
            for (int c = 0; c < 4; c++) acc[a][b2][c] = 0.f;

    float4 ra0, ra1, rb;
    const int lrow = tid >> 2, lc0 = (tid & 3) * 4;

    auto ldg_tile = [&](int kb) {
        const float* a = Ap + kb * BK;
        ra0 = *(const float4*)(a + (size_t)lrow * K2 + lc0);
        ra1 = *(const float4*)(a + (size_t)(lrow + 64) * K2 + lc0);
        rb  = *(const float4*)(Bp + kb * BK + (size_t)lrow * K2 + lc0);
    };
    auto sts_tile = [&](int s) {
        const float *p0 = (const float*)&ra0, *p1 = (const float*)&ra1;
        const float *pb = (const float*)&rb;
        #pragma unroll
        for (int j = 0; j < 4; j++) {
            As[s][lc0 + j][lrow]      = tf32r(p0[j]);
            As[s][lc0 + j][lrow + 64] = tf32r(p1[j]);
            Bs[s][lc0 + j][lrow]      = tf32r(pb[j]);
        }
    };
    auto compute = [&](int s) {
        #pragma unroll
        for (int ks = 0; ks < 2; ks++) {
            const int k0 = ks * 8;
            uint32_t a[2][4];
            #pragma unroll
            for (int mi = 0; mi < 2; mi++) {
                const int mb = wm * 32 + mi * 16;
                a[mi][0] = __float_as_uint(As[s][k0 + lt][mb + lg]);
                a[mi][1] = __float_as_uint(As[s][k0 + lt][mb + lg + 8]);
                a[mi][2] = __float_as_uint(As[s][k0 + 4 + lt][mb + lg]);
                a[mi][3] = __float_as_uint(As[s][k0 + 4 + lt][mb + lg + 8]);
            }
            #pragma unroll
            for (int ni = 0; ni < 4; ni++) {
                const int nb = wn * 32 + ni * 8;
                uint32_t bb[2];
                bb[0] = __float_as_uint(Bs[s][k0 + lt][nb + lg]);
                bb[1] = __float_as_uint(Bs[s][k0 + 4 + lt][nb + lg]);
                #pragma unroll
                for (int mi = 0; mi < 2; mi++) mma8(acc[mi][ni], a[mi], bb);
            }
        }
    };

    ldg_tile(0); sts_tile(0); __syncthreads();
    const int KIT = K2 / BK;
    for (int kb = 0; kb < KIT; kb++) {
        const int s = kb & 1;
        if (kb + 1 < KIT) ldg_tile(kb + 1);
        compute(s);
        if (kb + 1 < KIT) { sts_tile(s ^ 1); __syncthreads(); }
    }

    #pragma unroll
    for (int mi = 0; mi < 2; mi++)
        #pragma unroll
        for (int ni = 0; ni < 4; ni++) {
            const int r = mt * BM + wm * 32 + mi * 16 + lg;
            const int c = nt * BN + wn * 32 + ni * 8 + lt * 2;
            #pragma unroll
            for (int half = 0; half < 2; half++) {
                const int rr = r + half * 8;
                *(float2*)(g_xmcmp + (size_t)rr * C_ + c) =
                    make_float2(siluf(acc[mi][ni][half * 2]),
                                siluf(acc[mi][ni][half * 2 + 1]));
            }
        }
}

// ---------------- interleave (FROZEN) ----------------
__global__ __launch_bounds__(256)
void interleave_kernel(const float* __restrict__ x_m, float* __restrict__ out) {
    const int b = blockIdx.y, i = blockIdx.x, tid = threadIdx.x;
    if (i < TCMP) {
        const int dst = g_keepdst[b * TCMP + i];
        if (dst < 0) return;
        const float4* s = (const float4*)(g_xmcmp + ((size_t)(b * TCMP + i)) * C_);
        float4* d = (float4*)(out + ((size_t)(b * OUTLEN + dst)) * C_);
        for (int j = tid; j < C_ / 4; j += 256) d[j] = s[j];
    } else {
        const int k = i - TCMP;
        const int sk  = g_seqsel[b * NSEL + k];
        const int pos = sk + k;
        const int src = g_seldesc[b * NSEL + k];
        const float4* s = (const float4*)(x_m + ((size_t)(b * 2 * TCMP) + 2 * src) * C_);
        float4* d = (float4*)(out + ((size_t)(b * OUTLEN + pos)) * C_);
        for (int j = tid; j < 2 * C_ / 4; j += 256) d[j] = s[j];
    }
}

// ---------------- launch ----------------
extern "C" void kernel_launch(void* const* d_in, const int* in_sizes, int n_in,
                              void* d_out, int out_size) {
    const float* x_m = (const float*)d_in[0];
    const float* q_w = (const float*)d_in[1];
    const float* km  = (const float*)d_in[2];
    const float* Wg  = (const float*)d_in[3];
    const float* Wu  = (const float*)d_in[4];
    const float* Wd  = (const float*)d_in[5];
    float* out = (float*)d_out;

    cudaFuncSetAttribute(importance_kernel,
                         cudaFuncAttributeMaxDynamicSharedMemorySize, IMP_SMEM);

    importance_kernel<<<dim3(TW / IQ, B_ * H_), 512, IMP_SMEM>>>(q_w, km);
    reduce_h_kernel<<<(B_ * H_ * TCMP + 255) / 256, 256>>>();
    reduce_final_kernel<<<(B_ * TCMP + 255) / 256, 256>>>();
    rank_kernel<<<dim3(B_, TCMP / 256), 256>>>();
    topk_finalize_kernel<<<B_, 1024>>>();
    gemm1_kernel<<<2048, 256>>>(x_m, Wg, Wu);
    gemm2_kernel<<<2048, 256>>>(Wd);
    interleave_kernel<<<dim3(TCMP + NSEL, B_), 256>>>(x_m, out);
}

// round 16
// speedup vs baseline: 1.7941x; 1.0465x over previous
#include <cuda_runtime.h>
#include <cstdint>
#include <cstddef>

#define B_      4
#define TCMP    2048
#define C_      2048
#define H_      16
#define KV_     8
#define TW      1024
#define D_      128
#define NSEL    512
#define OUTLEN  2560
#define M_      (B_*TCMP)
#define K1      (2*C_)
#define K2      2048
#define SCALE_F 0.08838834764831845f

__device__ float  g_h[(size_t)M_ * C_];
__device__ float  g_xmcmp[(size_t)M_ * C_];
__device__ float  g_w[(size_t)B_ * H_ * TW * TCMP];   // 512 MB softmax weights
__device__ float  g_part[B_ * H_ * TCMP];
__device__ float  g_imp[B_ * TCMP];
__device__ int    g_rnk[B_ * TCMP];
__device__ int    g_seldesc[B_ * NSEL];
__device__ int    g_seqsel[B_ * NSEL];
__device__ int    g_keepdst[B_ * TCMP];

__device__ __forceinline__ float siluf(float x) { return x / (1.f + expf(-x)); }
__device__ __forceinline__ uint32_t f2tf(float x) {
    uint32_t u; asm("cvt.rna.tf32.f32 %0, %1;" : "=r"(u) : "f"(x)); return u;
}
__device__ __forceinline__ float tf32r(float x) {
    return __uint_as_float(f2tf(x));
}
__device__ __forceinline__ void mma8(float* c, const uint32_t* a, const uint32_t* b) {
    asm volatile("mma.sync.aligned.m16n8k8.row.col.f32.tf32.tf32.f32 "
                 "{%0,%1,%2,%3}, {%4,%5,%6,%7}, {%8,%9}, {%0,%1,%2,%3};"
                 : "+f"(c[0]), "+f"(c[1]), "+f"(c[2]), "+f"(c[3])
                 : "r"(a[0]), "r"(a[1]), "r"(a[2]), "r"(a[3]), "r"(b[0]), "r"(b[1]));
}

// ---------------- importance pass 1 (FROZEN numerics; v4 LDS, stride 36) ----------------
// Each acc[qi][j] accumulates in strictly ascending d (d-group unrolled in order):
// identical FFMA operand sequence per accumulator -> bit-identical to R13/R15.
#define IQ   16
#define KT   512
#define DC   32
#define KSTRIDE 36
#define QS_OFF   (IQ*TCMP)
#define KMS_OFF  (QS_OFF + IQ*D_)
#define IVZ_OFF  (KMS_OFF + KT*KSTRIDE)
#define IMP_SMEM ((IVZ_OFF + IQ) * 4)

__global__ __launch_bounds__(512, 1)
void importance_kernel(const float* __restrict__ q_w, const float* __restrict__ km) {
    extern __shared__ float sm[];
    const int tid = threadIdx.x;
    const int bh = blockIdx.y;
    const int b = bh >> 4, h = bh & 15;
    const int qbase = blockIdx.x * IQ;
    const float* qp = q_w + (((size_t)(b * H_ + h)) * TW + qbase) * D_;
    const float* kp = km + ((size_t)(b * KV_ + (h >> 1))) * TCMP * D_;

    for (int i = tid; i < IQ * D_ / 4; i += 512)
        ((float4*)(sm + QS_OFF))[i] = ((const float4*)qp)[i];

    const int qg = tid >> 7;       // 0..3  (4 q rows each)
    const int kg = tid & 127;      // 0..127 (4 k cols each, strided 128)
    float* sc  = sm;
    float* kms = sm + KMS_OFF;

    for (int kt = 0; kt < TCMP / KT; kt++) {
        float acc[4][4];
        #pragma unroll
        for (int qi = 0; qi < 4; qi++)
            #pragma unroll
            for (int j = 0; j < 4; j++) acc[qi][j] = 0.f;

        for (int dc = 0; dc < D_ / DC; dc++) {
            __syncthreads();
            for (int r = tid; r < KT; r += 512) {
                const float* src = kp + (size_t)(kt * KT + r) * D_ + dc * DC;
                #pragma unroll
                for (int f = 0; f < DC / 4; f++)
                    *(float4*)(kms + r * KSTRIDE + f * 4) = ((const float4*)src)[f];
            }
            __syncthreads();
            #pragma unroll
            for (int dg = 0; dg < DC; dg += 4) {
                float4 qv4[4];
                #pragma unroll
                for (int qi = 0; qi < 4; qi++)
                    qv4[qi] = *(const float4*)(sm + QS_OFF + (qg * 4 + qi) * D_ + dc * DC + dg);
                float4 kv4[4];
                #pragma unroll
                for (int j = 0; j < 4; j++)
                    kv4[j] = *(const float4*)(kms + (j * 128 + kg) * KSTRIDE + dg);
                #pragma unroll
                for (int dd = 0; dd < 4; dd++) {
                    #pragma unroll
                    for (int j = 0; j < 4; j++) {
                        float kv = (dd == 0) ? kv4[j].x : (dd == 1) ? kv4[j].y
                                 : (dd == 2) ? kv4[j].z : kv4[j].w;
                        #pragma unroll
                        for (int qi = 0; qi < 4; qi++) {
                            float qv = (dd == 0) ? qv4[qi].x : (dd == 1) ? qv4[qi].y
                                     : (dd == 2) ? qv4[qi].z : qv4[qi].w;
                            acc[qi][j] += qv * kv;
                        }
                    }
                }
            }
        }
        #pragma unroll
        for (int qi = 0; qi < 4; qi++)
            #pragma unroll
            for (int j = 0; j < 4; j++)
                sc[(qg * 4 + qi) * TCMP + kt * KT + j * 128 + kg] = acc[qi][j];
    }
    __syncthreads();

    const int warp = tid >> 5, lane = tid & 31;
    if (warp < IQ) {
        const int r = warp;
        float m = -1e30f;
        for (int i = lane; i < TCMP; i += 32) {
            float t = sc[r * TCMP + i] * SCALE_F;
            sc[r * TCMP + i] = t;
            m = fmaxf(m, t);
        }
        #pragma unroll
        for (int o = 16; o; o >>= 1) m = fmaxf(m, __shfl_xor_sync(~0u, m, o));
        float z = 0.f;
        for (int i = lane; i < TCMP; i += 32) {
            float e = expf(sc[r * TCMP + i] - m);
            sc[r * TCMP + i] = e;
            z += e;
        }
        #pragma unroll
        for (int o = 16; o; o >>= 1) z += __shfl_xor_sync(~0u, z, o);
        if (lane == 0) sm[IVZ_OFF + r] = z;
    }
    __syncthreads();

    float* wp = g_w + ((size_t)bh * TW + qbase) * TCMP;
    for (int idx = tid; idx < IQ * TCMP; idx += 512) {
        const int r = idx >> 11, k = idx & (TCMP - 1);
        wp[(size_t)r * TCMP + k] = sc[r * TCMP + k] / sm[IVZ_OFF + r];
    }
}

// ------- reduce: bit-identical to frozen order, parallelized per (b,h) -------
__global__ __launch_bounds__(256)
void reduce_h_kernel() {
    const int i = blockIdx.x * blockDim.x + threadIdx.x;
    if (i >= B_ * H_ * TCMP) return;
    const int k = i & (TCMP - 1);
    const int h = (i >> 11) & 15;
    const int b = i >> 15;
    const float* p = g_w + ((size_t)(b * H_ + h) * TW) * TCMP + k;
    float part[32];
    #pragma unroll
    for (int j = 0; j < 32; j++) part[j] = 0.f;
    for (int ii = 0; ii < 32; ii++) {
        #pragma unroll
        for (int j = 0; j < 32; j++)
            part[j] += p[(size_t)(j + 32 * ii) * TCMP];
    }
    #pragma unroll
    for (int off = 16; off >= 1; off >>= 1)
        #pragma unroll
        for (int j = 0; j < 16; j++)
            if (j < off) part[j] = part[j] + part[j + off];
    g_part[i] = part[0];
}

__global__ __launch_bounds__(256)
void reduce_final_kernel() {
    const int i = blockIdx.x * blockDim.x + threadIdx.x;
    if (i >= B_ * TCMP) return;
    const int b = i >> 11, k = i & (TCMP - 1);
    float S[16];
    #pragma unroll
    for (int h = 0; h < 16; h++) S[h] = g_part[(b * 16 + h) * TCMP + k];
    #pragma unroll
    for (int off = 8; off >= 1; off >>= 1)
        #pragma unroll
        for (int j = 0; j < 8; j++)
            if (j < off) S[j] = S[j] + S[j + off];
    g_imp[i] = S[0] / 16.f;
}

// ---------------- top-k: parallel rank + finalize (FROZEN semantics) ----------
__global__ __launch_bounds__(256)
void rank_kernel() {
    __shared__ float v[TCMP];
    const int b = blockIdx.x, seg = blockIdx.y, tid = threadIdx.x;
    for (int i = tid; i < TCMP; i += 256) v[i] = g_imp[b * TCMP + i];
    __syncthreads();
    const int t = seg * 256 + tid;
    float x = v[t];
    int r = 0;
    for (int j = 0; j < TCMP; j++) {
        float y = v[j];
        r += (y > x) || (y == x && j < t);
    }
    g_rnk[b * TCMP + t] = r;
}

__global__ __launch_bounds__(1024)
void topk_finalize_kernel() {
    __shared__ int rnk[TCMP];
    __shared__ int selm[TCMP];
    const int b = blockIdx.x, tid = threadIdx.x;
    for (int i = tid; i < TCMP; i += 1024) {
        rnk[i] = g_rnk[b * TCMP + i];
        selm[i] = (rnk[i] < NSEL);
    }
    __syncthreads();
    for (int t = tid; t < TCMP; t += 1024) {
        int cb = 0;
        for (int j = 0; j < t; j++) cb += selm[j];
        if (selm[t]) {
            g_seldesc[b * NSEL + rnk[t]] = t;
            g_seqsel[b * NSEL + cb] = t;
            g_keepdst[b * TCMP + t] = -1;
        } else {
            g_keepdst[b * TCMP + t] = t + cb;
        }
    }
}

// ---------------- GEMM 1: fused gate/up, 1xTF32, cvt at STS, single-sync pipe --------
#define BM 128
#define BN 64
#define BK 16

__global__ __launch_bounds__(256, 2)
void gemm1_kernel(const float* __restrict__ X,
                  const float* __restrict__ Wg, const float* __restrict__ Wu) {
    __shared__ float As[2][BK][BM + 4];
    __shared__ float Bs[2][2][BK][BN + 4];
    const int tid = threadIdx.x, bid = blockIdx.x;
    const int mt = (bid >> 9) * 16 + (bid & 15);
    const int nt = (bid >> 4) & 31;
    const float* Ap  = X  + (size_t)mt * BM * K1;
    const float* Bgp = Wg + (size_t)nt * BN * K1;
    const float* Bup = Wu + (size_t)nt * BN * K1;
    const int warp = tid >> 5, lane = tid & 31;
    const int wm = warp & 3, wn = warp >> 2;
    const int lt = lane & 3, lg = lane >> 2;

    float accG[2][4][4], accU[2][4][4];
    #pragma unroll
    for (int a = 0; a < 2; a++)
        #pragma unroll
        for (int b2 = 0; b2 < 4; b2++)
            #pragma unroll
            for (int c = 0; c < 4; c++) { accG[a][b2][c] = 0.f; accU[a][b2][c] = 0.f; }

    float4 ra0, ra1, rg, ru;
    const int lrow = tid >> 2, lc0 = (tid & 3) * 4;

    auto ldg_tile = [&](int kb) {
        const float* a = Ap + kb * BK;
        ra0 = *(const float4*)(a + (size_t)lrow * K1 + lc0);
        ra1 = *(const float4*)(a + (size_t)(lrow + 64) * K1 + lc0);
        rg  = *(const float4*)(Bgp + kb * BK + (size_t)lrow * K1 + lc0);
        ru  = *(const float4*)(Bup + kb * BK + (size_t)lrow * K1 + lc0);
    };
    auto sts_tile = [&](int s) {
        const float *p0 = (const float*)&ra0, *p1 = (const float*)&ra1;
        const float *pg = (const float*)&rg,  *pu = (const float*)&ru;
        #pragma unroll
        for (int j = 0; j < 4; j++) {
            As[s][lc0 + j][lrow]      = tf32r(p0[j]);
            As[s][lc0 + j][lrow + 64] = tf32r(p1[j]);
            Bs[s][0][lc0 + j][lrow]   = tf32r(pg[j]);
            Bs[s][1][lc0 + j][lrow]   = tf32r(pu[j]);
        }
    };
    auto compute = [&](int s) {
        #pragma unroll
        for (int ks = 0; ks < 2; ks++) {
            const int k0 = ks * 8;
            uint32_t a[2][4];
            #pragma unroll
            for (int mi = 0; mi < 2; mi++) {
                const int mb = wm * 32 + mi * 16;
                a[mi][0] = __float_as_uint(As[s][k0 + lt][mb + lg]);
                a[mi][1] = __float_as_uint(As[s][k0 + lt][mb + lg + 8]);
                a[mi][2] = __float_as_uint(As[s][k0 + 4 + lt][mb + lg]);
                a[mi][3] = __float_as_uint(As[s][k0 + 4 + lt][mb + lg + 8]);
            }
            #pragma unroll
            for (int ni = 0; ni < 4; ni++) {
                const int nb = wn * 32 + ni * 8;
                uint32_t bg[2], bu[2];
                bg[0] = __float_as_uint(Bs[s][0][k0 + lt][nb + lg]);
                bg[1] = __float_as_uint(Bs[s][0][k0 + 4 + lt][nb + lg]);
                bu[0] = __float_as_uint(Bs[s][1][k0 + lt][nb + lg]);
                bu[1] = __float_as_uint(Bs[s][1][k0 + 4 + lt][nb + lg]);
                #pragma unroll
                for (int mi = 0; mi < 2; mi++) {
                    mma8(accG[mi][ni], a[mi], bg);
                    mma8(accU[mi][ni], a[mi], bu);
                }
            }
        }
    };

    ldg_tile(0); sts_tile(0); __syncthreads();
    const int KIT = K1 / BK;
    for (int kb = 0; kb < KIT; kb++) {
        const int s = kb & 1;
        if (kb + 1 < KIT) ldg_tile(kb + 1);
        compute(s);
        if (kb + 1 < KIT) { sts_tile(s ^ 1); __syncthreads(); }
    }

    #pragma unroll
    for (int mi = 0; mi < 2; mi++)
        #pragma unroll
        for (int ni = 0; ni < 4; ni++) {
            const int r = mt * BM + wm * 32 + mi * 16 + lg;
            const int c = nt * BN + wn * 32 + ni * 8 + lt * 2;
            #pragma unroll
            for (int half = 0; half < 2; half++) {
                const int rr = r + half * 8;
                float g0 = accG[mi][ni][half * 2], g1 = accG[mi][ni][half * 2 + 1];
                float u0 = accU[mi][ni][half * 2], u1 = accU[mi][ni][half * 2 + 1];
                *(float2*)(g_h + (size_t)rr * C_ + c) =
                    make_float2(siluf(g0) * u0, siluf(g1) * u1);
            }
        }
}

// ---------------- GEMM 2: down-proj, 1xTF32, cvt at STS, single-sync pipe ----------
__global__ __launch_bounds__(256, 2)
void gemm2_kernel(const float* __restrict__ Wd) {
    __shared__ float As[2][BK][BM + 4];
    __shared__ float Bs[2][BK][BN + 4];
    const int tid = threadIdx.x, bid = blockIdx.x;
    const int nt = bid & 31, mt = bid >> 5;
    const float* Ap = g_h + (size_t)mt * BM * K2;
    const float* Bp = Wd  + (size_t)nt * BN * K2;
    const int warp = tid >> 5, lane = tid & 31;
    const int wm = warp & 3, wn = warp >> 2;
    const int lt = lane & 3, lg = lane >> 2;

    float acc[2][4][4];
    #pragma unroll
    for (int a = 0; a < 2; a++)
        #pragma unroll
        for (int b2 = 0; b2 < 4; b2++)
            #pragma unroll
            for (int c = 0; c < 4; c++) acc[a][b2][c] = 0.f;

    float4 ra0, ra1, rb;
    const int lrow = tid >> 2, lc0 = (tid & 3) * 4;

    auto ldg_tile = [&](int kb) {
        const float* a = Ap + kb * BK;
        ra0 = *(const float4*)(a + (size_t)lrow * K2 + lc0);
        ra1 = *(const float4*)(a + (size_t)(lrow + 64) * K2 + lc0);
        rb  = *(const float4*)(Bp + kb * BK + (size_t)lrow * K2 + lc0);
    };
    auto sts_tile = [&](int s) {
        const float *p0 = (const float*)&ra0, *p1 = (const float*)&ra1;
        const float *pb = (const float*)&rb;
        #pragma unroll
        for (int j = 0; j < 4; j++) {
            As[s][lc0 + j][lrow]      = tf32r(p0[j]);
            As[s][lc0 + j][lrow + 64] = tf32r(p1[j]);
            Bs[s][lc0 + j][lrow]      = tf32r(pb[j]);
        }
    };
    auto compute = [&](int s) {
        #pragma unroll
        for (int ks = 0; ks < 2; ks++) {
            const int k0 = ks * 8;
            uint32_t a[2][4];
            #pragma unroll
            for (int mi = 0; mi < 2; mi++) {
                const int mb = wm * 32 + mi * 16;
                a[mi][0] = __float_as_uint(As[s][k0 + lt][mb + lg]);
                a[mi][1] = __float_as_uint(As[s][k0 + lt][mb + lg + 8]);
                a[mi][2] = __float_as_uint(As[s][k0 + 4 + lt][mb + lg]);
                a[mi][3] = __float_as_uint(As[s][k0 + 4 + lt][mb + lg + 8]);
            }
            #pragma unroll
            for (int ni = 0; ni < 4; ni++) {
                const int nb = wn * 32 + ni * 8;
                uint32_t bb[2];
                bb[0] = __float_as_uint(Bs[s][k0 + lt][nb + lg]);
                bb[1] = __float_as_uint(Bs[s][k0 + 4 + lt][nb + lg]);
                #pragma unroll
                for (int mi = 0; mi < 2; mi++) mma8(acc[mi][ni], a[mi], bb);
            }
        }
    };

    ldg_tile(0); sts_tile(0); __syncthreads();
    const int KIT = K2 / BK;
    for (int kb = 0; kb < KIT; kb++) {
        const int s = kb & 1;
        if (kb + 1 < KIT) ldg_tile(kb + 1);
        compute(s);
        if (kb + 1 < KIT) { sts_tile(s ^ 1); __syncthreads(); }
    }

    #pragma unroll
    for (int mi = 0; mi < 2; mi++)
        #pragma unroll
        for (int ni = 0; ni < 4; ni++) {
            const int r = mt * BM + wm * 32 + mi * 16 + lg;
            const int c = nt * BN + wn * 32 + ni * 8 + lt * 2;
            #pragma unroll
            for (int half = 0; half < 2; half++) {
                const int rr = r + half * 8;
                *(float2*)(g_xmcmp + (size_t)rr * C_ + c) =
                    make_float2(siluf(acc[mi][ni][half * 2]),
                                siluf(acc[mi][ni][half * 2 + 1]));
            }
        }
}

// ---------------- interleave (FROZEN) ----------------
__global__ __launch_bounds__(256)
void interleave_kernel(const float* __restrict__ x_m, float* __restrict__ out) {
    const int b = blockIdx.y, i = blockIdx.x, tid = threadIdx.x;
    if (i < TCMP) {
        const int dst = g_keepdst[b * TCMP + i];
        if (dst < 0) return;
        const float4* s = (const float4*)(g_xmcmp + ((size_t)(b * TCMP + i)) * C_);
        float4* d = (float4*)(out + ((size_t)(b * OUTLEN + dst)) * C_);
        for (int j = tid; j < C_ / 4; j += 256) d[j] = s[j];
    } else {
        const int k = i - TCMP;
        const int sk  = g_seqsel[b * NSEL + k];
        const int pos = sk + k;
        const int src = g_seldesc[b * NSEL + k];
        const float4* s = (const float4*)(x_m + ((size_t)(b * 2 * TCMP) + 2 * src) * C_);
        float4* d = (float4*)(out + ((size_t)(b * OUTLEN + pos)) * C_);
        for (int j = tid; j < 2 * C_ / 4; j += 256) d[j] = s[j];
    }
}

// ---------------- launch ----------------
extern "C" void kernel_launch(void* const* d_in, const int* in_sizes, int n_in,
                              void* d_out, int out_size) {
    const float* x_m = (const float*)d_in[0];
    const float* q_w = (const float*)d_in[1];
    const float* km  = (const float*)d_in[2];
    const float* Wg  = (const float*)d_in[3];
    const float* Wu  = (const float*)d_in[4];
    const float* Wd  = (const float*)d_in[5];
    float* out = (float*)d_out;

    cudaFuncSetAttribute(importance_kernel,
                         cudaFuncAttributeMaxDynamicSharedMemorySize, IMP_SMEM);

    importance_kernel<<<dim3(TW / IQ, B_ * H_), 512, IMP_SMEM>>>(q_w, km);
    reduce_h_kernel<<<(B_ * H_ * TCMP + 255) / 256, 256>>>();
    reduce_final_kernel<<<(B_ * TCMP + 255) / 256, 256>>>();
    rank_kernel<<<dim3(B_, TCMP / 256), 256>>>();
    topk_finalize_kernel<<<B_, 1024>>>();
    gemm1_kernel<<<2048, 256>>>(x_m, Wg, Wu);
    gemm2_kernel<<<2048, 256>>>(Wd);
    interleave_kernel<<<dim3(TCMP + NSEL, B_), 256>>>(x_m, out);
}

// round 17
// speedup vs baseline: 1.8928x; 1.0550x over previous
#include <cuda_runtime.h>
#include <cstdint>
#include <cstddef>

#define B_      4
#define TCMP    2048
#define C_      2048
#define H_      16
#define KV_     8
#define TW      1024
#define D_      128
#define NSEL    512
#define OUTLEN  2560
#define M_      (B_*TCMP)
#define K1      (2*C_)
#define K2      2048
#define SCALE_F 0.08838834764831845f

__device__ float  g_h[(size_t)M_ * C_];
__device__ float  g_xmcmp[(size_t)M_ * C_];
__device__ float  g_w[(size_t)B_ * H_ * TW * TCMP];   // 512 MB softmax weights
__device__ float  g_part[B_ * H_ * TCMP];
__device__ float  g_imp[B_ * TCMP];
__device__ int    g_rnk[B_ * TCMP];
__device__ int    g_seldesc[B_ * NSEL];
__device__ int    g_seqsel[B_ * NSEL];
__device__ int    g_keepdst[B_ * TCMP];

__device__ __forceinline__ float siluf(float x) { return x / (1.f + expf(-x)); }
__device__ __forceinline__ uint32_t f2tf(float x) {
    uint32_t u; asm("cvt.rna.tf32.f32 %0, %1;" : "=r"(u) : "f"(x)); return u;
}
__device__ __forceinline__ float tf32r(float x) {
    return __uint_as_float(f2tf(x));
}
__device__ __forceinline__ void mma8(float* c, const uint32_t* a, const uint32_t* b) {
    asm volatile("mma.sync.aligned.m16n8k8.row.col.f32.tf32.tf32.f32 "
                 "{%0,%1,%2,%3}, {%4,%5,%6,%7}, {%8,%9}, {%0,%1,%2,%3};"
                 : "+f"(c[0]), "+f"(c[1]), "+f"(c[2]), "+f"(c[3])
                 : "r"(a[0]), "r"(a[1]), "r"(a[2]), "r"(a[3]), "r"(b[0]), "r"(b[1]));
}

// ---------------- importance pass 1 (FROZEN numerics; v4 LDS, stride 36) ----------------
#define IQ   16
#define KT   512
#define DC   32
#define KSTRIDE 36
#define QS_OFF   (IQ*TCMP)
#define KMS_OFF  (QS_OFF + IQ*D_)
#define IVZ_OFF  (KMS_OFF + KT*KSTRIDE)
#define IMP_SMEM ((IVZ_OFF + IQ) * 4)

__global__ __launch_bounds__(512, 1)
void importance_kernel(const float* __restrict__ q_w, const float* __restrict__ km) {
    extern __shared__ float sm[];
    const int tid = threadIdx.x;
    const int bh = blockIdx.y;
    const int b = bh >> 4, h = bh & 15;
    const int qbase = blockIdx.x * IQ;
    const float* qp = q_w + (((size_t)(b * H_ + h)) * TW + qbase) * D_;
    const float* kp = km + ((size_t)(b * KV_ + (h >> 1))) * TCMP * D_;

    for (int i = tid; i < IQ * D_ / 4; i += 512)
        ((float4*)(sm + QS_OFF))[i] = ((const float4*)qp)[i];

    const int qg = tid >> 7;
    const int kg = tid & 127;
    float* sc  = sm;
    float* kms = sm + KMS_OFF;

    for (int kt = 0; kt < TCMP / KT; kt++) {
        float acc[4][4];
        #pragma unroll
        for (int qi = 0; qi < 4; qi++)
            #pragma unroll
            for (int j = 0; j < 4; j++) acc[qi][j] = 0.f;

        for (int dc = 0; dc < D_ / DC; dc++) {
            __syncthreads();
            for (int r = tid; r < KT; r += 512) {
                const float* src = kp + (size_t)(kt * KT + r) * D_ + dc * DC;
                #pragma unroll
                for (int f = 0; f < DC / 4; f++)
                    *(float4*)(kms + r * KSTRIDE + f * 4) = ((const float4*)src)[f];
            }
            __syncthreads();
            #pragma unroll
            for (int dg = 0; dg < DC; dg += 4) {
                float4 qv4[4];
                #pragma unroll
                for (int qi = 0; qi < 4; qi++)
                    qv4[qi] = *(const float4*)(sm + QS_OFF + (qg * 4 + qi) * D_ + dc * DC + dg);
                float4 kv4[4];
                #pragma unroll
                for (int j = 0; j < 4; j++)
                    kv4[j] = *(const float4*)(kms + (j * 128 + kg) * KSTRIDE + dg);
                #pragma unroll
                for (int dd = 0; dd < 4; dd++) {
                    #pragma unroll
                    for (int j = 0; j < 4; j++) {
                        float kv = (dd == 0) ? kv4[j].x : (dd == 1) ? kv4[j].y
                                 : (dd == 2) ? kv4[j].z : kv4[j].w;
                        #pragma unroll
                        for (int qi = 0; qi < 4; qi++) {
                            float qv = (dd == 0) ? qv4[qi].x : (dd == 1) ? qv4[qi].y
                                     : (dd == 2) ? qv4[qi].z : qv4[qi].w;
                            acc[qi][j] += qv * kv;
                        }
                    }
                }
            }
        }
        #pragma unroll
        for (int qi = 0; qi < 4; qi++)
            #pragma unroll
            for (int j = 0; j < 4; j++)
                sc[(qg * 4 + qi) * TCMP + kt * KT + j * 128 + kg] = acc[qi][j];
    }
    __syncthreads();

    const int warp = tid >> 5, lane = tid & 31;
    if (warp < IQ) {
        const int r = warp;
        float m = -1e30f;
        for (int i = lane; i < TCMP; i += 32) {
            float t = sc[r * TCMP + i] * SCALE_F;
            sc[r * TCMP + i] = t;
            m = fmaxf(m, t);
        }
        #pragma unroll
        for (int o = 16; o; o >>= 1) m = fmaxf(m, __shfl_xor_sync(~0u, m, o));
        float z = 0.f;
        for (int i = lane; i < TCMP; i += 32) {
            float e = expf(sc[r * TCMP + i] - m);
            sc[r * TCMP + i] = e;
            z += e;
        }
        #pragma unroll
        for (int o = 16; o; o >>= 1) z += __shfl_xor_sync(~0u, z, o);
        if (lane == 0) sm[IVZ_OFF + r] = z;
    }
    __syncthreads();

    float* wp = g_w + ((size_t)bh * TW + qbase) * TCMP;
    for (int idx = tid; idx < IQ * TCMP; idx += 512) {
        const int r = idx >> 11, k = idx & (TCMP - 1);
        wp[(size_t)r * TCMP + k] = sc[r * TCMP + k] / sm[IVZ_OFF + r];
    }
}

// ------- reduce: bit-identical to frozen order, parallelized per (b,h) -------
__global__ __launch_bounds__(256)
void reduce_h_kernel() {
    const int i = blockIdx.x * blockDim.x + threadIdx.x;
    if (i >= B_ * H_ * TCMP) return;
    const int k = i & (TCMP - 1);
    const int h = (i >> 11) & 15;
    const int b = i >> 15;
    const float* p = g_w + ((size_t)(b * H_ + h) * TW) * TCMP + k;
    float part[32];
    #pragma unroll
    for (int j = 0; j < 32; j++) part[j] = 0.f;
    for (int ii = 0; ii < 32; ii++) {
        #pragma unroll
        for (int j = 0; j < 32; j++)
            part[j] += p[(size_t)(j + 32 * ii) * TCMP];
    }
    #pragma unroll
    for (int off = 16; off >= 1; off >>= 1)
        #pragma unroll
        for (int j = 0; j < 16; j++)
            if (j < off) part[j] = part[j] + part[j + off];
    g_part[i] = part[0];
}

__global__ __launch_bounds__(256)
void reduce_final_kernel() {
    const int i = blockIdx.x * blockDim.x + threadIdx.x;
    if (i >= B_ * TCMP) return;
    const int b = i >> 11, k = i & (TCMP - 1);
    float S[16];
    #pragma unroll
    for (int h = 0; h < 16; h++) S[h] = g_part[(b * 16 + h) * TCMP + k];
    #pragma unroll
    for (int off = 8; off >= 1; off >>= 1)
        #pragma unroll
        for (int j = 0; j < 8; j++)
            if (j < off) S[j] = S[j] + S[j + off];
    g_imp[i] = S[0] / 16.f;
}

// ---------------- top-k: parallel rank + finalize (FROZEN semantics) ----------
__global__ __launch_bounds__(256)
void rank_kernel() {
    __shared__ float v[TCMP];
    const int b = blockIdx.x, seg = blockIdx.y, tid = threadIdx.x;
    for (int i = tid; i < TCMP; i += 256) v[i] = g_imp[b * TCMP + i];
    __syncthreads();
    const int t = seg * 256 + tid;
    float x = v[t];
    int r = 0;
    for (int j = 0; j < TCMP; j++) {
        float y = v[j];
        r += (y > x) || (y == x && j < t);
    }
    g_rnk[b * TCMP + t] = r;
}

__global__ __launch_bounds__(1024)
void topk_finalize_kernel() {
    __shared__ int rnk[TCMP];
    __shared__ int selm[TCMP];
    const int b = blockIdx.x, tid = threadIdx.x;
    for (int i = tid; i < TCMP; i += 1024) {
        rnk[i] = g_rnk[b * TCMP + i];
        selm[i] = (rnk[i] < NSEL);
    }
    __syncthreads();
    for (int t = tid; t < TCMP; t += 1024) {
        int cb = 0;
        for (int j = 0; j < t; j++) cb += selm[j];
        if (selm[t]) {
            g_seldesc[b * NSEL + rnk[t]] = t;
            g_seqsel[b * NSEL + cb] = t;
            g_keepdst[b * TCMP + t] = -1;
        } else {
            g_keepdst[b * TCMP + t] = t + cb;
        }
    }
}

// ---------------- GEMM 1: fused gate/up, 1xTF32, conflict-free fragment LDS ----------
#define BM 128
#define BN 64
#define BK 16
#define PAD 8

__global__ __launch_bounds__(256, 2)
void gemm1_kernel(const float* __restrict__ X,
                  const float* __restrict__ Wg, const float* __restrict__ Wu) {
    __shared__ float As[2][BK][BM + PAD];
    __shared__ float Bs[2][2][BK][BN + PAD];
    const int tid = threadIdx.x, bid = blockIdx.x;
    const int mt = (bid >> 9) * 16 + (bid & 15);
    const int nt = (bid >> 4) & 31;
    const float* Ap  = X  + (size_t)mt * BM * K1;
    const float* Bgp = Wg + (size_t)nt * BN * K1;
    const float* Bup = Wu + (size_t)nt * BN * K1;
    const int warp = tid >> 5, lane = tid & 31;
    const int wm = warp & 3, wn = warp >> 2;
    const int lt = lane & 3, lg = lane >> 2;

    float accG[2][4][4], accU[2][4][4];
    #pragma unroll
    for (int a = 0; a < 2; a++)
        #pragma unroll
        for (int b2 = 0; b2 < 4; b2++)
            #pragma unroll
            for (int c = 0; c < 4; c++) { accG[a][b2][c] = 0.f; accU[a][b2][c] = 0.f; }

    float4 ra0, ra1, rg, ru;
    const int lrow = tid >> 2, lc0 = (tid & 3) * 4;

    auto ldg_tile = [&](int kb) {
        const float* a = Ap + kb * BK;
        ra0 = *(const float4*)(a + (size_t)lrow * K1 + lc0);
        ra1 = *(const float4*)(a + (size_t)(lrow + 64) * K1 + lc0);
        rg  = *(const float4*)(Bgp + kb * BK + (size_t)lrow * K1 + lc0);
        ru  = *(const float4*)(Bup + kb * BK + (size_t)lrow * K1 + lc0);
    };
    auto sts_tile = [&](int s) {
        const float *p0 = (const float*)&ra0, *p1 = (const float*)&ra1;
        const float *pg = (const float*)&rg,  *pu = (const float*)&ru;
        #pragma unroll
        for (int j = 0; j < 4; j++) {
            As[s][lc0 + j][lrow]      = tf32r(p0[j]);
            As[s][lc0 + j][lrow + 64] = tf32r(p1[j]);
            Bs[s][0][lc0 + j][lrow]   = tf32r(pg[j]);
            Bs[s][1][lc0 + j][lrow]   = tf32r(pu[j]);
        }
    };
    auto compute = [&](int s) {
        #pragma unroll
        for (int ks = 0; ks < 2; ks++) {
            const int k0 = ks * 8;
            uint32_t a[2][4];
            #pragma unroll
            for (int mi = 0; mi < 2; mi++) {
                const int mb = wm * 32 + mi * 16;
                a[mi][0] = __float_as_uint(As[s][k0 + lt][mb + lg]);
                a[mi][1] = __float_as_uint(As[s][k0 + lt][mb + lg + 8]);
                a[mi][2] = __float_as_uint(As[s][k0 + 4 + lt][mb + lg]);
                a[mi][3] = __float_as_uint(As[s][k0 + 4 + lt][mb + lg + 8]);
            }
            #pragma unroll
            for (int ni = 0; ni < 4; ni++) {
                const int nb = wn * 32 + ni * 8;
                uint32_t bg[2], bu[2];
                bg[0] = __float_as_uint(Bs[s][0][k0 + lt][nb + lg]);
                bg[1] = __float_as_uint(Bs[s][0][k0 + 4 + lt][nb + lg]);
                bu[0] = __float_as_uint(Bs[s][1][k0 + lt][nb + lg]);
                bu[1] = __float_as_uint(Bs[s][1][k0 + 4 + lt][nb + lg]);
                #pragma unroll
                for (int mi = 0; mi < 2; mi++) {
                    mma8(accG[mi][ni], a[mi], bg);
                    mma8(accU[mi][ni], a[mi], bu);
                }
            }
        }
    };

    ldg_tile(0); sts_tile(0); __syncthreads();
    const int KIT = K1 / BK;
    for (int kb = 0; kb < KIT; kb++) {
        const int s = kb & 1;
        if (kb + 1 < KIT) ldg_tile(kb + 1);
        compute(s);
        if (kb + 1 < KIT) { sts_tile(s ^ 1); __syncthreads(); }
    }

    #pragma unroll
    for (int mi = 0; mi < 2; mi++)
        #pragma unroll
        for (int ni = 0; ni < 4; ni++) {
            const int r = mt * BM + wm * 32 + mi * 16 + lg;
            const int c = nt * BN + wn * 32 + ni * 8 + lt * 2;
            #pragma unroll
            for (int half = 0; half < 2; half++) {
                const int rr = r + half * 8;
                float g0 = accG[mi][ni][half * 2], g1 = accG[mi][ni][half * 2 + 1];
                float u0 = accU[mi][ni][half * 2], u1 = accU[mi][ni][half * 2 + 1];
                *(float2*)(g_h + (size_t)rr * C_ + c) =
                    make_float2(siluf(g0) * u0, siluf(g1) * u1);
            }
        }
}

// ---------------- GEMM 2: down-proj, 1xTF32, conflict-free fragment LDS ----------
__global__ __launch_bounds__(256, 2)
void gemm2_kernel(const float* __restrict__ Wd) {
    __shared__ float As[2][BK][BM + PAD];
    __shared__ float Bs[2][BK][BN + PAD];
    const int tid = threadIdx.x, bid = blockIdx.x;
    const int nt = bid & 31, mt = bid >> 5;
    const float* Ap = g_h + (size_t)mt * BM * K2;
    const float* Bp = Wd  + (size_t)nt * BN * K2;
    const int warp = tid >> 5, lane = tid & 31;
    const int wm = warp & 3, wn = warp >> 2;
    const int lt = lane & 3, lg = lane >> 2;

    float acc[2][4][4];
    #pragma unroll
    for (int a = 0; a < 2; a++)
        #pragma unroll
        for (int b2 = 0; b2 < 4; b2++)
            #pragma unroll
            for (int c = 0; c < 4; c++) acc[a][b2][c] = 0.f;

    float4 ra0, ra1, rb;
    const int lrow = tid >> 2, lc0 = (tid & 3) * 4;

    auto ldg_tile = [&](int kb) {
        const float* a = Ap + kb * BK;
        ra0 = *(const float4*)(a + (size_t)lrow * K2 + lc0);
        ra1 = *(const float4*)(a + (size_t)(lrow + 64) * K2 + lc0);
        rb  = *(const float4*)(Bp + kb * BK + (size_t)lrow * K2 + lc0);
    };
    auto sts_tile = [&](int s) {
        const float *p0 = (const float*)&ra0, *p1 = (const float*)&ra1;
        const float *pb = (const float*)&rb;
        #pragma unroll
        for (int j = 0; j < 4; j++) {
            As[s][lc0 + j][lrow]      = tf32r(p0[j]);
            As[s][lc0 + j][lrow + 64] = tf32r(p1[j]);
            Bs[s][lc0 + j][lrow]      = tf32r(pb[j]);
        }
    };
    auto compute = [&](int s) {
        #pragma unroll
        for (int ks = 0; ks < 2; ks++) {
            const int k0 = ks * 8;
            uint32_t a[2][4];
            #pragma unroll
            for (int mi = 0; mi < 2; mi++) {
                const int mb = wm * 32 + mi * 16;
                a[mi][0] = __float_as_uint(As[s][k0 + lt][mb + lg]);
                a[mi][1] = __float_as_uint(As[s][k0 + lt][mb + lg + 8]);
                a[mi][2] = __float_as_uint(As[s][k0 + 4 + lt][mb + lg]);
                a[mi][3] = __float_as_uint(As[s][k0 + 4 + lt][mb + lg + 8]);
            }
            #pragma unroll
            for (int ni = 0; ni < 4; ni++) {
                const int nb = wn * 32 + ni * 8;
                uint32_t bb[2];
                bb[0] = __float_as_uint(Bs[s][k0 + lt][nb + lg]);
                bb[1] = __float_as_uint(Bs[s][k0 + 4 + lt][nb + lg]);
                #pragma unroll
                for (int mi = 0; mi < 2; mi++) mma8(acc[mi][ni], a[mi], bb);
            }
        }
    };

    ldg_tile(0); sts_tile(0); __syncthreads();
    const int KIT = K2 / BK;
    for (int kb = 0; kb < KIT; kb++) {
        const int s = kb & 1;
        if (kb + 1 < KIT) ldg_tile(kb + 1);
        compute(s);
        if (kb + 1 < KIT) { sts_tile(s ^ 1); __syncthreads(); }
    }

    #pragma unroll
    for (int mi = 0; mi < 2; mi++)
        #pragma unroll
        for (int ni = 0; ni < 4; ni++) {
            const int r = mt * BM + wm * 32 + mi * 16 + lg;
            const int c = nt * BN + wn * 32 + ni * 8 + lt * 2;
            #pragma unroll
            for (int half = 0; half < 2; half++) {
                const int rr = r + half * 8;
                *(float2*)(g_xmcmp + (size_t)rr * C_ + c) =
                    make_float2(siluf(acc[mi][ni][half * 2]),
                                siluf(acc[mi][ni][half * 2 + 1]));
            }
        }
}

// ---------------- interleave (FROZEN) ----------------
__global__ __launch_bounds__(256)
void interleave_kernel(const float* __restrict__ x_m, float* __restrict__ out) {
    const int b = blockIdx.y, i = blockIdx.x, tid = threadIdx.x;
    if (i < TCMP) {
        const int dst = g_keepdst[b * TCMP + i];
        if (dst < 0) return;
        const float4* s = (const float4*)(g_xmcmp + ((size_t)(b * TCMP + i)) * C_);
        float4* d = (float4*)(out + ((size_t)(b * OUTLEN + dst)) * C_);
        for (int j = tid; j < C_ / 4; j += 256) d[j] = s[j];
    } else {
        const int k = i - TCMP;
        const int sk  = g_seqsel[b * NSEL + k];
        const int pos = sk + k;
        const int src = g_seldesc[b * NSEL + k];
        const float4* s = (const float4*)(x_m + ((size_t)(b * 2 * TCMP) + 2 * src) * C_);
        float4* d = (float4*)(out + ((size_t)(b * OUTLEN + pos)) * C_);
        for (int j = tid; j < 2 * C_ / 4; j += 256) d[j] = s[j];
    }
}

// ---------------- launch ----------------
extern "C" void kernel_launch(void* const* d_in, const int* in_sizes, int n_in,
                              void* d_out, int out_size) {
    const float* x_m = (const float*)d_in[0];
    const float* q_w = (const float*)d_in[1];
    const float* km  = (const float*)d_in[2];
    const float* Wg  = (const float*)d_in[3];
    const float* Wu  = (const float*)d_in[4];
    const float* Wd  = (const float*)d_in[5];
    float* out = (float*)d_out;

    cudaFuncSetAttribute(importance_kernel,
                         cudaFuncAttributeMaxDynamicSharedMemorySize, IMP_SMEM);

    importance_kernel<<<dim3(TW / IQ, B_ * H_), 512, IMP_SMEM>>>(q_w, km);
    reduce_h_kernel<<<(B_ * H_ * TCMP + 255) / 256, 256>>>();
    reduce_final_kernel<<<(B_ * TCMP + 255) / 256, 256>>>();
    rank_kernel<<<dim3(B_, TCMP / 256), 256>>>();
    topk_finalize_kernel<<<B_, 1024>>>();
    gemm1_kernel<<<2048, 256>>>(x_m, Wg, Wu);
    gemm2_kernel<<<2048, 256>>>(Wd);
    interleave_kernel<<<dim3(TCMP + NSEL, B_), 256>>>(x_m, out);
}